// round 2
// baseline (speedup 1.0000x reference)
#include <cuda_runtime.h>
#include <cuda_bf16.h>
#include <math.h>

// Problem constants
#define NN_ 10000
#define DD_ 128
#define KSEL 5000

// GEMM tiling
#define BJ 128
#define BK 16
#define KSPL 8
#define NTILES 625          // NN_/BK

// deg partials
#define DEG_CHUNKS 16
#define DEG_ROWS   625      // NN_/DEG_CHUNKS

// Output layout (float32, concatenated in reference return order)
#define OFF_XPOOL   ((size_t)0)
#define OFF_ADJ     ((size_t)KSEL * DD_)                       // 640000
#define OFF_MOTIF   (OFF_ADJ + (size_t)KSEL * KSEL)            // 25,640,000
#define OFF_SCORES  (OFF_MOTIF + (size_t)KSEL * KSEL)          // 50,640,000
#define OFF_TOPIDX  (OFF_SCORES + (size_t)NN_)                 // 50,650,000

// ---------------- device scratch (no runtime allocation allowed) ----------------
__device__ float g_WT[DD_ * DD_];                // W^T  (WT[e][d] = W[d][e])
__device__ float g_part[DEG_CHUNKS * NN_];       // deg partial sums
__device__ float g_dinv[NN_];
__device__ float g_z[(size_t)NN_ * DD_];         // z = dinv_i * (x W^T)[i]
__device__ float g_Upart[KSPL][(size_t)NN_ * DD_];
__device__ float g_h[(size_t)NN_ * DD_];
__device__ float g_scores[NN_];
__device__ int   g_topidx[KSEL];

// ---------------- helpers ----------------
__device__ __forceinline__ void cp16(void* smem, const void* gmem, int src_bytes) {
    unsigned a = (unsigned)__cvta_generic_to_shared(smem);
    asm volatile("cp.async.ca.shared.global [%0], [%1], 16, %2;\n"
                 :: "r"(a), "l"(gmem), "r"(src_bytes) : "memory");
}
__device__ __forceinline__ void cp_commit() {
    asm volatile("cp.async.commit_group;\n" ::: "memory");
}
template<int NPEND>
__device__ __forceinline__ void cp_wait() {
    asm volatile("cp.async.wait_group %0;\n" :: "n"(NPEND) : "memory");
}
__device__ __forceinline__ unsigned long long splat2(float a) {
    unsigned long long r;
    asm("mov.b64 %0, {%1, %1};" : "=l"(r) : "f"(a));
    return r;
}
__device__ __forceinline__ void fma2(unsigned long long& acc,
                                     unsigned long long a, unsigned long long b) {
    asm("fma.rn.f32x2 %0, %1, %2, %0;" : "+l"(acc) : "l"(a), "l"(b));
}

// ---------------- K0: W transpose ----------------
__global__ void k_transW(const float* __restrict__ W) {
    int t = blockIdx.x * blockDim.x + threadIdx.x;
    if (t < DD_ * DD_) {
        int e = t >> 7, d = t & 127;
        g_WT[e * DD_ + d] = W[d * DD_ + e];
    }
}

// ---------------- K1: deg partial column sums ----------------
__global__ void k_deg_part(const float* __restrict__ motif) {
    int j = blockIdx.x * 256 + threadIdx.x;
    int c = blockIdx.y;
    if (j >= NN_) return;
    int i0 = c * DEG_ROWS, i1 = i0 + DEG_ROWS;
    float s0 = 0.f, s1 = 0.f, s2 = 0.f, s3 = 0.f;
    int i = i0;
    for (; i + 4 <= i1; i += 4) {
        s0 += motif[(size_t)(i    ) * NN_ + j];
        s1 += motif[(size_t)(i + 1) * NN_ + j];
        s2 += motif[(size_t)(i + 2) * NN_ + j];
        s3 += motif[(size_t)(i + 3) * NN_ + j];
    }
    for (; i < i1; ++i) s0 += motif[(size_t)i * NN_ + j];
    g_part[c * NN_ + j] = (s0 + s1) + (s2 + s3);
}

__global__ void k_deg_fin() {
    int j = blockIdx.x * 256 + threadIdx.x;
    if (j >= NN_) return;
    float d = 1.0f;                      // +I contributes 1 to each column sum
    #pragma unroll
    for (int c = 0; c < DEG_CHUNKS; ++c) d += g_part[c * NN_ + j];
    g_dinv[j] = 1.0f / sqrtf(d);        // deg >= 1 always
}

// ---------------- K2: z = dinv * (x @ W^T) ----------------
__global__ __launch_bounds__(128) void k_z(const float* __restrict__ x) {
    __shared__ float xs[32][DD_];
    int i0 = blockIdx.x * 32;
    int tid = threadIdx.x;          // = d
    for (int l = tid; l < 32 * DD_; l += 128) {
        int r = l >> 7, e = l & 127;
        xs[r][e] = (i0 + r < NN_) ? x[(size_t)(i0 + r) * DD_ + e] : 0.f;
    }
    __syncthreads();
    float acc[32];
    #pragma unroll
    for (int r = 0; r < 32; ++r) acc[r] = 0.f;
    #pragma unroll 4
    for (int e = 0; e < DD_; ++e) {
        float w = g_WT[e * DD_ + tid];
        #pragma unroll
        for (int r = 0; r < 32; ++r) acc[r] += xs[r][e] * w;
    }
    for (int r = 0; r < 32; ++r) {
        int i = i0 + r;
        if (i < NN_) g_z[(size_t)i * DD_ + tid] = g_dinv[i] * acc[r];
    }
}

// ---------------- K3: big GEMM  U[j,d] = sum_i motif[i,j] * z[i,d] ----------------
__device__ __forceinline__ void gemm_load(float* As, float* Bs,
                                          int ktile, const float* __restrict__ motif,
                                          int J0, int widthJ, int tid) {
    int i0 = ktile * BK;
    #pragma unroll
    for (int q = 0; q < 2; ++q) {                 // motif tile: 512 x 16B chunks
        int c  = tid + q * 256;
        int kk = c >> 5, j4 = c & 31;
        bool valid = (j4 * 4 < widthJ);
        const float* src = valid ? (motif + (size_t)(i0 + kk) * NN_ + (J0 + j4 * 4))
                                 : motif;
        cp16(As + kk * BJ + j4 * 4, src, valid ? 16 : 0);
    }
    #pragma unroll
    for (int q = 0; q < 2; ++q) {                 // z tile
        int c  = tid + q * 256;
        int kk = c >> 5, j4 = c & 31;
        cp16(Bs + kk * DD_ + j4 * 4, g_z + (size_t)(i0 + kk) * DD_ + j4 * 4, 16);
    }
}

__global__ __launch_bounds__(256) void k_gemm(const float* __restrict__ motif) {
    __shared__ float As[2][BK * BJ];
    __shared__ float Bs[2][BK * DD_];
    int J0  = blockIdx.x * BJ;
    int spl = blockIdx.y;
    int t0 = (spl * NTILES) / KSPL;
    int t1 = ((spl + 1) * NTILES) / KSPL;
    int tid = threadIdx.x;
    int tj = tid >> 4, td = tid & 15;
    int widthJ = NN_ - J0; if (widthJ > BJ) widthJ = BJ;

    unsigned long long acc[8][4];
    #pragma unroll
    for (int u = 0; u < 8; ++u)
        #pragma unroll
        for (int v = 0; v < 4; ++v) acc[u][v] = 0ull;

    int nt = t1 - t0;
    gemm_load(As[0], Bs[0], t0, motif, J0, widthJ, tid);
    cp_commit();

    for (int tt = 0; tt < nt; ++tt) {
        int cur = tt & 1;
        if (tt + 1 < nt) {
            gemm_load(As[cur ^ 1], Bs[cur ^ 1], t0 + tt + 1, motif, J0, widthJ, tid);
            cp_commit();
            cp_wait<1>();
        } else {
            cp_wait<0>();
        }
        __syncthreads();
        const float* A = As[cur];
        const float* B = Bs[cur];
        #pragma unroll
        for (int kk = 0; kk < BK; ++kk) {
            unsigned long long a2[8], b2[4];
            #pragma unroll
            for (int u = 0; u < 8; ++u) a2[u] = splat2(A[kk * BJ + tj * 8 + u]);
            #pragma unroll
            for (int v = 0; v < 4; ++v)
                b2[v] = *reinterpret_cast<const unsigned long long*>(&B[kk * DD_ + td * 8 + v * 2]);
            #pragma unroll
            for (int u = 0; u < 8; ++u)
                #pragma unroll
                for (int v = 0; v < 4; ++v) fma2(acc[u][v], a2[u], b2[v]);
        }
        __syncthreads();
    }

    float* Up = g_Upart[spl];
    #pragma unroll
    for (int u = 0; u < 8; ++u) {
        int j = J0 + tj * 8 + u;
        if (j < NN_) {
            #pragma unroll
            for (int v = 0; v < 4; ++v)
                *reinterpret_cast<unsigned long long*>(&Up[(size_t)j * DD_ + td * 8 + v * 2]) = acc[u][v];
        }
    }
}

// ---------------- K4: epilogue — h = tanh(dinv*(U+z)+b), scores ----------------
__global__ __launch_bounds__(256) void k_epi(const float* __restrict__ b_gcn,
                                             const float* __restrict__ w_score,
                                             const float* __restrict__ b_score,
                                             float* __restrict__ out_scores) {
    int warp = threadIdx.x >> 5;
    int lane = threadIdx.x & 31;
    int j = blockIdx.x * 8 + warp;
    if (j >= NN_) return;
    float dj = g_dinv[j];
    float ssum = 0.f;
    #pragma unroll
    for (int q = 0; q < 4; ++q) {
        int d = lane + 32 * q;
        size_t off = (size_t)j * DD_ + d;
        float u = 0.f;
        #pragma unroll
        for (int s = 0; s < KSPL; ++s) u += g_Upart[s][off];
        u += g_z[off];
        float hh = tanhf(dj * u + b_gcn[d]);
        g_h[off] = hh;
        ssum += hh * w_score[d];
    }
    #pragma unroll
    for (int o = 16; o; o >>= 1) ssum += __shfl_down_sync(0xffffffffu, ssum, o);
    if (lane == 0) {
        float sc = ssum + b_score[0];
        g_scores[j] = sc;
        out_scores[j] = sc;
    }
}

// ---------------- K5: exact top-k (k=5000) selection, single block ----------------
__global__ __launch_bounds__(1024) void k_select(float* __restrict__ out_topidx_f) {
    __shared__ unsigned keys[NN_];       // 40 KB
    __shared__ unsigned hist[256];
    __shared__ unsigned sc[1024];
    __shared__ unsigned sh_prefix, sh_r, sh_cg;
    int tid = threadIdx.x;

    for (int i = tid; i < NN_; i += 1024) {
        unsigned u = __float_as_uint(g_scores[i]);
        u = (u & 0x80000000u) ? ~u : (u | 0x80000000u);   // monotone ascending map
        keys[i] = u;
    }
    if (tid == 0) { sh_prefix = 0u; sh_r = KSEL; sh_cg = 0u; }
    __syncthreads();

    // radix-select: value of the k-th largest key
    for (int p = 3; p >= 0; --p) {
        if (tid < 256) hist[tid] = 0u;
        __syncthreads();
        unsigned msk  = (p == 3) ? 0u : (0xFFFFFFFFu << (8 * (p + 1)));
        unsigned pref = sh_prefix;
        for (int i = tid; i < NN_; i += 1024) {
            unsigned kk = keys[i];
            if ((kk & msk) == pref) atomicAdd(&hist[(kk >> (8 * p)) & 255], 1u);
        }
        __syncthreads();
        if (tid == 0) {
            unsigned r = sh_r, c = 0; int b = 0;
            for (b = 255; b >= 0; --b) {
                if (c + hist[b] >= r) break;
                c += hist[b];
            }
            sh_r = r - c;
            sh_prefix = pref | ((unsigned)b << (8 * p));
        }
        __syncthreads();
    }
    unsigned T = sh_prefix;

    // count strictly greater
    {
        unsigned c = 0;
        for (int i = tid; i < NN_; i += 1024) c += (keys[i] > T);
        atomicAdd(&sh_cg, c);
    }
    __syncthreads();
    unsigned ties_needed = KSEL - sh_cg;

    // per-thread contiguous ranges of 10 elements
    int base = tid * 10;
    int end  = base + 10; if (end > NN_) end = NN_;
    if (base > NN_) base = NN_;

    // tie-rank exclusive scan
    unsigned tc = 0;
    for (int i = base; i < end; ++i) tc += (keys[i] == T);
    sc[tid] = tc; __syncthreads();
    for (int off = 1; off < 1024; off <<= 1) {
        unsigned v = (tid >= off) ? sc[tid - off] : 0u;
        __syncthreads(); sc[tid] += v; __syncthreads();
    }
    unsigned tie_excl = sc[tid] - tc;
    __syncthreads();

    // selection-count exclusive scan
    unsigned scnt = 0;
    {
        unsigned tr = tie_excl;
        for (int i = base; i < end; ++i) {
            unsigned kk = keys[i];
            bool tie = (kk == T);
            bool sel = (kk > T) || (tie && tr < ties_needed);
            tr += tie; scnt += sel;
        }
    }
    sc[tid] = scnt; __syncthreads();
    for (int off = 1; off < 1024; off <<= 1) {
        unsigned v = (tid >= off) ? sc[tid - off] : 0u;
        __syncthreads(); sc[tid] += v; __syncthreads();
    }
    unsigned pos = sc[tid] - scnt;
    {
        unsigned tr = tie_excl;
        for (int i = base; i < end; ++i) {
            unsigned kk = keys[i];
            bool tie = (kk == T);
            bool sel = (kk > T) || (tie && tr < ties_needed);
            tr += tie;
            if (sel) {
                g_topidx[pos] = i;
                out_topidx_f[pos] = (float)i;
                ++pos;
            }
        }
    }
}

// ---------------- K6: x_pool gather ----------------
__global__ void k_xpool(float* __restrict__ out_x) {
    int e = blockIdx.x * 256 + threadIdx.x;     // 640000 elements
    if (e >= KSEL * DD_) return;
    int r = e >> 7, d = e & 127;
    out_x[e] = g_h[(size_t)g_topidx[r] * DD_ + d];
}

// ---------------- K7: adjacency_pool & motif_pool gathers ----------------
__global__ void k_pool(const float* __restrict__ adjacency,
                       const float* __restrict__ motif,
                       float* __restrict__ out_adj,
                       float* __restrict__ out_motif) {
    int c = blockIdx.x * 256 + threadIdx.x;
    int r = blockIdx.y;
    if (c >= KSEL) return;
    int ri = g_topidx[r];
    int ci = g_topidx[c];
    size_t src = (size_t)ri * NN_ + ci;
    size_t dst = (size_t)r * KSEL + c;
    out_adj[dst]   = adjacency[src];
    out_motif[dst] = motif[src];
}

// ---------------- launch ----------------
extern "C" void kernel_launch(void* const* d_in, const int* in_sizes, int n_in,
                              void* d_out, int out_size) {
    const float* x       = (const float*)d_in[0];
    const float* adj     = (const float*)d_in[1];
    const float* motif   = (const float*)d_in[2];
    const float* W_gcn   = (const float*)d_in[3];
    const float* b_gcn   = (const float*)d_in[4];
    const float* w_score = (const float*)d_in[5];
    const float* b_score = (const float*)d_in[6];
    float* out = (float*)d_out;

    float* out_x      = out + OFF_XPOOL;
    float* out_adj    = out + OFF_ADJ;
    float* out_motif  = out + OFF_MOTIF;
    float* out_scores = out + OFF_SCORES;
    float* out_tif    = out + OFF_TOPIDX;

    k_transW<<<16, 1024>>>(W_gcn);
    k_deg_part<<<dim3(40, DEG_CHUNKS), 256>>>(motif);
    k_deg_fin<<<40, 256>>>();
    k_z<<<313, 128>>>(x);
    k_gemm<<<dim3(79, KSPL), 256>>>(motif);
    k_epi<<<1250, 256>>>(b_gcn, w_score, b_score, out_scores);
    k_select<<<1, 1024>>>(out_tif);
    k_xpool<<<2500, 256>>>(out_x);
    k_pool<<<dim3(20, KSEL), 256>>>(adj, motif, out_adj, out_motif);
}

// round 4
// speedup vs baseline: 1.2526x; 1.2526x over previous
#include <cuda_runtime.h>
#include <cuda_bf16.h>
#include <math.h>
#include <stdint.h>

// Problem constants
#define NN_ 10000
#define DD_ 128
#define KSEL 5000

// GEMM config
#define NJT 79              // j tiles of 128
#define KSPL 16             // k splits
#define NUNITS (NJT * KSPL) // 1264
#define NCHUNK 313          // 32-i chunks covering 10016
#define GRID_GEMM 148

// deg partials
#define DEG_CHUNKS 16
#define DEG_ROWS   625

// Output layout (float32, reference return order)
#define OFF_XPOOL   ((size_t)0)
#define OFF_ADJ     ((size_t)KSEL * DD_)
#define OFF_MOTIF   (OFF_ADJ + (size_t)KSEL * KSEL)
#define OFF_SCORES  (OFF_MOTIF + (size_t)KSEL * KSEL)
#define OFF_TOPIDX  (OFF_SCORES + (size_t)NN_)

// ---------------- device scratch ----------------
__device__ float g_WT[DD_ * DD_];
__device__ float g_part[DEG_CHUNKS * NN_];
__device__ float g_dinv[NN_];
__device__ float g_z[(size_t)NN_ * DD_];                 // plain layout (epilogue +I term)
__device__ float g_zfrag[(size_t)NCHUNK * 8192];         // fragment layout hi/lo (~10MB)
__device__ float g_Upart[KSPL][(size_t)NN_ * DD_];       // split-K partials (~82MB)
__device__ float g_h[(size_t)NN_ * DD_];
__device__ float g_scores[NN_];
__device__ int   g_topidx[KSEL];

// ---------------- helpers ----------------
__device__ __forceinline__ void cp16(void* smem, const void* gmem) {
    unsigned a = (unsigned)__cvta_generic_to_shared(smem);
    asm volatile("cp.async.ca.shared.global [%0], [%1], 16;\n" :: "r"(a), "l"(gmem) : "memory");
}
__device__ __forceinline__ void cp_commit() {
    asm volatile("cp.async.commit_group;\n" ::: "memory");
}
template<int NPEND>
__device__ __forceinline__ void cp_wait() {
    asm volatile("cp.async.wait_group %0;\n" :: "n"(NPEND) : "memory");
}
__device__ __forceinline__ float hi13(float v) {        // tf32-exact high part
    return __uint_as_float(__float_as_uint(v) & 0xFFFFE000u);
}
// D(16x8,f32) += A(16x8,tf32) * B(8x8,tf32)
__device__ __forceinline__ void mma8(float4& d, const float4& a, const float2& b) {
    asm volatile(
        "mma.sync.aligned.m16n8k8.row.col.f32.tf32.tf32.f32 "
        "{%0,%1,%2,%3}, {%4,%5,%6,%7}, {%8,%9}, {%0,%1,%2,%3};\n"
        : "+f"(d.x), "+f"(d.y), "+f"(d.z), "+f"(d.w)
        : "r"(__float_as_uint(a.x)), "r"(__float_as_uint(a.y)),
          "r"(__float_as_uint(a.z)), "r"(__float_as_uint(a.w)),
          "r"(__float_as_uint(b.x)), "r"(__float_as_uint(b.y)));
}

// ---------------- K0: W transpose ----------------
__global__ void k_transW(const float* __restrict__ W) {
    int t = blockIdx.x * blockDim.x + threadIdx.x;
    if (t < DD_ * DD_) {
        int e = t >> 7, d = t & 127;
        g_WT[e * DD_ + d] = W[d * DD_ + e];
    }
}

// ---------------- K1: deg column sums ----------------
__global__ void k_deg_part(const float* __restrict__ motif) {
    int j = blockIdx.x * 256 + threadIdx.x;
    int c = blockIdx.y;
    if (j >= NN_) return;
    int i0 = c * DEG_ROWS, i1 = i0 + DEG_ROWS;
    float s0 = 0.f, s1 = 0.f, s2 = 0.f, s3 = 0.f;
    int i = i0;
    for (; i + 4 <= i1; i += 4) {
        s0 += motif[(size_t)(i    ) * NN_ + j];
        s1 += motif[(size_t)(i + 1) * NN_ + j];
        s2 += motif[(size_t)(i + 2) * NN_ + j];
        s3 += motif[(size_t)(i + 3) * NN_ + j];
    }
    for (; i < i1; ++i) s0 += motif[(size_t)i * NN_ + j];
    g_part[c * NN_ + j] = (s0 + s1) + (s2 + s3);
}

__global__ void k_deg_fin() {
    int j = blockIdx.x * 256 + threadIdx.x;
    if (j >= NN_) return;
    float d = 1.0f;
    #pragma unroll
    for (int c = 0; c < DEG_CHUNKS; ++c) d += g_part[c * NN_ + j];
    g_dinv[j] = 1.0f / sqrtf(d);
}

// ---------------- K2: z = dinv*(x@W^T); also emit fragment-layout hi/lo ----------------
// Fragment layout per 32-i chunk ic (8192 floats):
//   idx = ic*8192 + term*4096 + (nt*4 + ks)*64 + lane*2 + b
//   nt = d>>3, ks = r>>3, kk = r&7, b = kk>>2, lane = (d&7)*4 + (kk&3)
__global__ __launch_bounds__(128) void k_z(const float* __restrict__ x) {
    __shared__ float xs[32][DD_];
    int i0 = blockIdx.x * 32;
    int tid = threadIdx.x;              // = d
    for (int l = tid; l < 32 * DD_; l += 128) {
        int r = l >> 7, e = l & 127;
        xs[r][e] = (i0 + r < NN_) ? x[(size_t)(i0 + r) * DD_ + e] : 0.f;
    }
    __syncthreads();
    float acc[32];
    #pragma unroll
    for (int r = 0; r < 32; ++r) acc[r] = 0.f;
    #pragma unroll 4
    for (int e = 0; e < DD_; ++e) {
        float w = g_WT[e * DD_ + tid];
        #pragma unroll
        for (int r = 0; r < 32; ++r) acc[r] += xs[r][e] * w;
    }
    int nt = tid >> 3;
    int lbase = (tid & 7) * 4;
    size_t fb = (size_t)blockIdx.x * 8192;
    #pragma unroll
    for (int r = 0; r < 32; ++r) {
        int i = i0 + r;
        float zv = 0.f;
        if (i < NN_) {
            zv = g_dinv[i] * acc[r];
            g_z[(size_t)i * DD_ + tid] = zv;
        }
        float zh = hi13(zv), zl = zv - zh;
        int ks = r >> 3, kk = r & 7;
        int b = kk >> 2;
        int lane = lbase + (kk & 3);
        size_t o = fb + (size_t)((nt * 4 + ks) * 64 + lane * 2 + b);
        g_zfrag[o]        = zh;
        g_zfrag[o + 4096] = zl;
    }
}

// ---------------- K3: persistent mma.sync tf32x3 GEMM ----------------
// U[j,d] = sum_i motif[i,j] * z[i,d]
// SMEM per stage: A frags 32KB ([term][mt8][ks4][lane32][4]f), B frags 32KB
#define STAGE_BYTES 65536
#define GEMM_SMEM   (2 * STAGE_BYTES)

__device__ __forceinline__ float ldm(const float* __restrict__ m, int i, int j) {
    return (i < NN_ && j < NN_) ? __ldg(&m[(size_t)i * NN_ + j]) : 0.f;
}

__device__ __forceinline__ void prefetchA(float* apre, const float* __restrict__ motif,
                                          int ic, int J0, int w, int row, int cb) {
    int j = J0 + w * 16 + row;
    int ib = ic * 32 + cb;
    #pragma unroll
    for (int ks = 0; ks < 4; ++ks) {
        int i = ib + ks * 8;
        apre[ks * 4 + 0] = ldm(motif, i,     j);
        apre[ks * 4 + 1] = ldm(motif, i,     j + 8);
        apre[ks * 4 + 2] = ldm(motif, i + 4, j);
        apre[ks * 4 + 3] = ldm(motif, i + 4, j + 8);
    }
}

__global__ __launch_bounds__(256, 1) void k_gemm_mma(const float* __restrict__ motif) {
    extern __shared__ char sm[];
    int tid = threadIdx.x;
    int w = tid >> 5, l = tid & 31;
    int wm = w & 1, wn = w >> 1;
    int row = l >> 2, cb = l & 3;

    for (int u = blockIdx.x; u < NUNITS; u += GRID_GEMM) {
        int jt = u % NJT, ksp = u / NJT;
        int J0 = jt * 128;
        int c0 = (ksp * NCHUNK) / KSPL;
        int c1 = ((ksp + 1) * NCHUNK) / KSPL;
        int nch = c1 - c0;

        float4 acc[4][4];
        #pragma unroll
        for (int a = 0; a < 4; ++a)
            #pragma unroll
            for (int b = 0; b < 4; ++b) acc[a][b] = make_float4(0.f, 0.f, 0.f, 0.f);

        float apre[16];
        prefetchA(apre, motif, c0, J0, w, row, cb);
        {   // cp.async B chunk c0 -> stage 0
            const float* src = g_zfrag + (size_t)c0 * 8192;
            char* Bs = sm + 32768;
            #pragma unroll
            for (int q = 0; q < 8; ++q)
                cp16(Bs + (tid + q * 256) * 16, src + (size_t)(tid + q * 256) * 4);
            cp_commit();
        }

        for (int cc = 0; cc < nch; ++cc) {
            int s = cc & 1;
            char* As = sm + s * STAGE_BYTES;
            char* Bs = As + 32768;

            // STS A(cc) fragments (hi/lo split)
            #pragma unroll
            for (int ks = 0; ks < 4; ++ks) {
                float4 hi, lo;
                float v0 = apre[ks * 4 + 0], v1 = apre[ks * 4 + 1];
                float v2 = apre[ks * 4 + 2], v3 = apre[ks * 4 + 3];
                hi.x = hi13(v0); lo.x = v0 - hi.x;
                hi.y = hi13(v1); lo.y = v1 - hi.y;
                hi.z = hi13(v2); lo.z = v2 - hi.z;
                hi.w = hi13(v3); lo.w = v3 - hi.w;
                *(float4*)(As +         (w * 4 + ks) * 512 + l * 16) = hi;
                *(float4*)(As + 16384 + (w * 4 + ks) * 512 + l * 16) = lo;
            }

            if (cc + 1 < nch) {
                prefetchA(apre, motif, c0 + cc + 1, J0, w, row, cb);
                const float* src = g_zfrag + (size_t)(c0 + cc + 1) * 8192;
                char* Bn = sm + (s ^ 1) * STAGE_BYTES + 32768;
                #pragma unroll
                for (int q = 0; q < 8; ++q)
                    cp16(Bn + (tid + q * 256) * 16, src + (size_t)(tid + q * 256) * 4);
                cp_commit();
                cp_wait<1>();
            } else {
                cp_wait<0>();
            }
            __syncthreads();

            // MMA over this chunk: 4 k-steps x 4x4 tiles x 3 split terms
            #pragma unroll
            for (int ks = 0; ks < 4; ++ks) {
                float2 bh[4], bl[4];
                float4 ah[4], al[4];
                #pragma unroll
                for (int ntl = 0; ntl < 4; ++ntl) {
                    int bo = ((wn * 4 + ntl) * 4 + ks) * 256 + l * 8;
                    bh[ntl] = *(const float2*)(Bs + bo);
                    bl[ntl] = *(const float2*)(Bs + 16384 + bo);
                }
                #pragma unroll
                for (int mtl = 0; mtl < 4; ++mtl) {
                    int ao = ((wm * 4 + mtl) * 4 + ks) * 512 + l * 16;
                    ah[mtl] = *(const float4*)(As + ao);
                    al[mtl] = *(const float4*)(As + 16384 + ao);
                }
                #pragma unroll
                for (int mtl = 0; mtl < 4; ++mtl)
                    #pragma unroll
                    for (int ntl = 0; ntl < 4; ++ntl) {
                        mma8(acc[mtl][ntl], ah[mtl], bh[ntl]);
                        mma8(acc[mtl][ntl], ah[mtl], bl[ntl]);
                        mma8(acc[mtl][ntl], al[mtl], bh[ntl]);
                    }
            }
            __syncthreads();
        }

        // epilogue: write partials
        float* Up = g_Upart[ksp];
        #pragma unroll
        for (int mtl = 0; mtl < 4; ++mtl) {
            int r0 = J0 + wm * 64 + mtl * 16 + row;
            #pragma unroll
            for (int ntl = 0; ntl < 4; ++ntl) {
                int d0 = wn * 32 + ntl * 8 + cb * 2;
                float4 a = acc[mtl][ntl];
                if (r0 < NN_)     *(float2*)&Up[(size_t)r0 * 128 + d0]       = make_float2(a.x, a.y);
                if (r0 + 8 < NN_) *(float2*)&Up[(size_t)(r0 + 8) * 128 + d0] = make_float2(a.z, a.w);
            }
        }
        __syncthreads();
    }
}

// ---------------- K4: epilogue — h = tanh(dinv*(U+z)+b), scores ----------------
__global__ __launch_bounds__(256) void k_epi(const float* __restrict__ b_gcn,
                                             const float* __restrict__ w_score,
                                             const float* __restrict__ b_score,
                                             float* __restrict__ out_scores) {
    int warp = threadIdx.x >> 5;
    int lane = threadIdx.x & 31;
    int j = blockIdx.x * 8 + warp;
    if (j >= NN_) return;
    float dj = g_dinv[j];
    float ssum = 0.f;
    #pragma unroll
    for (int q = 0; q < 4; ++q) {
        int d = lane + 32 * q;
        size_t off = (size_t)j * DD_ + d;
        float u = 0.f;
        #pragma unroll
        for (int s = 0; s < KSPL; ++s) u += g_Upart[s][off];
        u += g_z[off];
        float hh = tanhf(dj * u + b_gcn[d]);
        g_h[off] = hh;
        ssum += hh * w_score[d];
    }
    #pragma unroll
    for (int o = 16; o; o >>= 1) ssum += __shfl_down_sync(0xffffffffu, ssum, o);
    if (lane == 0) {
        float sc = ssum + b_score[0];
        g_scores[j] = sc;
        out_scores[j] = sc;
    }
}

// ---------------- K5: exact top-k selection ----------------
__global__ __launch_bounds__(1024) void k_select(float* __restrict__ out_topidx_f) {
    __shared__ unsigned keys[NN_];
    __shared__ unsigned hist[256];
    __shared__ unsigned sc[1024];
    __shared__ unsigned sh_prefix, sh_r, sh_cg;
    int tid = threadIdx.x;

    for (int i = tid; i < NN_; i += 1024) {
        unsigned u = __float_as_uint(g_scores[i]);
        u = (u & 0x80000000u) ? ~u : (u | 0x80000000u);
        keys[i] = u;
    }
    if (tid == 0) { sh_prefix = 0u; sh_r = KSEL; sh_cg = 0u; }
    __syncthreads();

    for (int p = 3; p >= 0; --p) {
        if (tid < 256) hist[tid] = 0u;
        __syncthreads();
        unsigned msk  = (p == 3) ? 0u : (0xFFFFFFFFu << (8 * (p + 1)));
        unsigned pref = sh_prefix;
        for (int i = tid; i < NN_; i += 1024) {
            unsigned kk = keys[i];
            if ((kk & msk) == pref) atomicAdd(&hist[(kk >> (8 * p)) & 255], 1u);
        }
        __syncthreads();
        if (tid == 0) {
            unsigned r = sh_r, c = 0; int b = 0;
            for (b = 255; b >= 0; --b) {
                if (c + hist[b] >= r) break;
                c += hist[b];
            }
            sh_r = r - c;
            sh_prefix = pref | ((unsigned)b << (8 * p));
        }
        __syncthreads();
    }
    unsigned T = sh_prefix;

    {
        unsigned c = 0;
        for (int i = tid; i < NN_; i += 1024) c += (keys[i] > T);
        atomicAdd(&sh_cg, c);
    }
    __syncthreads();
    unsigned ties_needed = KSEL - sh_cg;

    int base = tid * 10;
    int end  = base + 10; if (end > NN_) end = NN_;
    if (base > NN_) base = NN_;

    unsigned tc = 0;
    for (int i = base; i < end; ++i) tc += (keys[i] == T);
    sc[tid] = tc; __syncthreads();
    for (int off = 1; off < 1024; off <<= 1) {
        unsigned v = (tid >= off) ? sc[tid - off] : 0u;
        __syncthreads(); sc[tid] += v; __syncthreads();
    }
    unsigned tie_excl = sc[tid] - tc;
    __syncthreads();

    unsigned scnt = 0;
    {
        unsigned tr = tie_excl;
        for (int i = base; i < end; ++i) {
            unsigned kk = keys[i];
            bool tie = (kk == T);
            bool sel = (kk > T) || (tie && tr < ties_needed);
            tr += tie; scnt += sel;
        }
    }
    sc[tid] = scnt; __syncthreads();
    for (int off = 1; off < 1024; off <<= 1) {
        unsigned v = (tid >= off) ? sc[tid - off] : 0u;
        __syncthreads(); sc[tid] += v; __syncthreads();
    }
    unsigned pos = sc[tid] - scnt;
    {
        unsigned tr = tie_excl;
        for (int i = base; i < end; ++i) {
            unsigned kk = keys[i];
            bool tie = (kk == T);
            bool sel = (kk > T) || (tie && tr < ties_needed);
            tr += tie;
            if (sel) {
                g_topidx[pos] = i;
                out_topidx_f[pos] = (float)i;
                ++pos;
            }
        }
    }
}

// ---------------- K6: x_pool gather ----------------
__global__ void k_xpool(float* __restrict__ out_x) {
    int e = blockIdx.x * 256 + threadIdx.x;
    if (e >= KSEL * DD_) return;
    int r = e >> 7, d = e & 127;
    out_x[e] = g_h[(size_t)g_topidx[r] * DD_ + d];
}

// ---------------- K7: adjacency_pool & motif_pool gathers ----------------
__global__ void k_pool(const float* __restrict__ adjacency,
                       const float* __restrict__ motif,
                       float* __restrict__ out_adj,
                       float* __restrict__ out_motif) {
    int c = blockIdx.x * 256 + threadIdx.x;
    int r = blockIdx.y;
    if (c >= KSEL) return;
    int ri = g_topidx[r];
    int ci = g_topidx[c];
    size_t src = (size_t)ri * NN_ + ci;
    size_t dst = (size_t)r * KSEL + c;
    out_adj[dst]   = adjacency[src];
    out_motif[dst] = motif[src];
}

// ---------------- launch ----------------
extern "C" void kernel_launch(void* const* d_in, const int* in_sizes, int n_in,
                              void* d_out, int out_size) {
    const float* x       = (const float*)d_in[0];
    const float* adj     = (const float*)d_in[1];
    const float* motif   = (const float*)d_in[2];
    const float* W_gcn   = (const float*)d_in[3];
    const float* b_gcn   = (const float*)d_in[4];
    const float* w_score = (const float*)d_in[5];
    const float* b_score = (const float*)d_in[6];
    float* out = (float*)d_out;

    float* out_x      = out + OFF_XPOOL;
    float* out_adj    = out + OFF_ADJ;
    float* out_motif  = out + OFF_MOTIF;
    float* out_scores = out + OFF_SCORES;
    float* out_tif    = out + OFF_TOPIDX;

    cudaFuncSetAttribute(k_gemm_mma, cudaFuncAttributeMaxDynamicSharedMemorySize, GEMM_SMEM);

    k_transW<<<16, 1024>>>(W_gcn);
    k_deg_part<<<dim3(40, DEG_CHUNKS), 256>>>(motif);
    k_deg_fin<<<40, 256>>>();
    k_z<<<NCHUNK, 128>>>(x);
    k_gemm_mma<<<GRID_GEMM, 256, GEMM_SMEM>>>(motif);
    k_epi<<<1250, 256>>>(b_gcn, w_score, b_score, out_scores);
    k_select<<<1, 1024>>>(out_tif);
    k_xpool<<<2500, 256>>>(out_x);
    k_pool<<<dim3(20, KSEL), 256>>>(adj, motif, out_adj, out_motif);
}

// round 8
// speedup vs baseline: 1.2925x; 1.0318x over previous
#include <cuda_runtime.h>
#include <cuda_bf16.h>
#include <math.h>
#include <stdint.h>

// Problem constants
#define NN_ 10000
#define DD_ 128
#define KSEL 5000

// GEMM config
#define NJT 79              // j tiles of 128
#define KSPL 16             // k splits
#define NUNITS (NJT * KSPL) // 1264
#define NCHUNK 313          // 32-i chunks covering 10016
#define GRID_GEMM 148

// deg partials
#define DEG_CHUNKS 16
#define DEG_ROWS   625

// Output layout (float32, reference return order)
#define OFF_XPOOL   ((size_t)0)
#define OFF_ADJ     ((size_t)KSEL * DD_)
#define OFF_MOTIF   (OFF_ADJ + (size_t)KSEL * KSEL)
#define OFF_SCORES  (OFF_MOTIF + (size_t)KSEL * KSEL)
#define OFF_TOPIDX  (OFF_SCORES + (size_t)NN_)

// ---------------- device scratch ----------------
__device__ float g_WT[DD_ * DD_];
__device__ float g_part[DEG_CHUNKS * NN_];
__device__ float g_dinv[NN_];
__device__ float g_z[(size_t)NN_ * DD_];                 // plain layout (epilogue +I term)
__device__ float g_zfrag[(size_t)NCHUNK * 8192];         // fragment layout hi/lo (~10MB)
__device__ float g_Upart[KSPL][(size_t)NN_ * DD_];       // split-K partials (~82MB)
__device__ float g_h[(size_t)NN_ * DD_];
__device__ float g_scores[NN_];
__device__ int   g_topidx[KSEL];

// ---------------- helpers ----------------
__device__ __forceinline__ void cp16(void* smem, const void* gmem) {
    unsigned a = (unsigned)__cvta_generic_to_shared(smem);
    asm volatile("cp.async.ca.shared.global [%0], [%1], 16;\n" :: "r"(a), "l"(gmem) : "memory");
}
__device__ __forceinline__ void cp_commit() {
    asm volatile("cp.async.commit_group;\n" ::: "memory");
}
template<int NPEND>
__device__ __forceinline__ void cp_wait() {
    asm volatile("cp.async.wait_group %0;\n" :: "n"(NPEND) : "memory");
}
__device__ __forceinline__ float hi13(float v) {        // tf32-exact high part
    return __uint_as_float(__float_as_uint(v) & 0xFFFFE000u);
}
// D(16x8,f32) += A(16x8,tf32) * B(8x8,tf32)
__device__ __forceinline__ void mma8(float4& d, const float4& a, const float2& b) {
    asm volatile(
        "mma.sync.aligned.m16n8k8.row.col.f32.tf32.tf32.f32 "
        "{%0,%1,%2,%3}, {%4,%5,%6,%7}, {%8,%9}, {%0,%1,%2,%3};\n"
        : "+f"(d.x), "+f"(d.y), "+f"(d.z), "+f"(d.w)
        : "r"(__float_as_uint(a.x)), "r"(__float_as_uint(a.y)),
          "r"(__float_as_uint(a.z)), "r"(__float_as_uint(a.w)),
          "r"(__float_as_uint(b.x)), "r"(__float_as_uint(b.y)));
}

// ---------------- K0: W transpose ----------------
__global__ void k_transW(const float* __restrict__ W) {
    int t = blockIdx.x * blockDim.x + threadIdx.x;
    if (t < DD_ * DD_) {
        int e = t >> 7, d = t & 127;
        g_WT[e * DD_ + d] = W[d * DD_ + e];
    }
}

// ---------------- K1: deg column sums ----------------
__global__ void k_deg_part(const float* __restrict__ motif) {
    int j = blockIdx.x * 256 + threadIdx.x;
    int c = blockIdx.y;
    if (j >= NN_) return;
    int i0 = c * DEG_ROWS, i1 = i0 + DEG_ROWS;
    float s0 = 0.f, s1 = 0.f, s2 = 0.f, s3 = 0.f;
    int i = i0;
    for (; i + 4 <= i1; i += 4) {
        s0 += motif[(size_t)(i    ) * NN_ + j];
        s1 += motif[(size_t)(i + 1) * NN_ + j];
        s2 += motif[(size_t)(i + 2) * NN_ + j];
        s3 += motif[(size_t)(i + 3) * NN_ + j];
    }
    for (; i < i1; ++i) s0 += motif[(size_t)i * NN_ + j];
    g_part[c * NN_ + j] = (s0 + s1) + (s2 + s3);
}

__global__ void k_deg_fin() {
    int j = blockIdx.x * 256 + threadIdx.x;
    if (j >= NN_) return;
    float d = 1.0f;
    #pragma unroll
    for (int c = 0; c < DEG_CHUNKS; ++c) d += g_part[c * NN_ + j];
    g_dinv[j] = 1.0f / sqrtf(d);
}

// ---------------- K2: z = dinv*(x@W^T); emit plain + fragment hi/lo ----------------
// 16 rows per block, x staged transposed so the inner loop is 4x LDS.128 broadcast.
// Fragment layout per 32-i chunk ic (8192 floats):
//   idx = ic*8192 + term*4096 + (nt*4 + ks)*64 + lane*2 + b
//   nt = d>>3, ks = rc>>3, kk = rc&7, b = kk>>2, lane = (d&7)*4 + (kk&3), rc = i&31
#define ZROWS 16
__global__ __launch_bounds__(128) void k_z(const float* __restrict__ x) {
    __shared__ float xst[DD_][20];       // [e][r], pad 20 (80B rows, 16B-aligned)
    int i0 = blockIdx.x * ZROWS;
    int tid = threadIdx.x;               // = d
    for (int l = tid; l < ZROWS * DD_; l += 128) {
        int r = l >> 7, e = l & 127;
        xst[e][r] = (i0 + r < NN_) ? x[(size_t)(i0 + r) * DD_ + e] : 0.f;
    }
    __syncthreads();

    float acc[ZROWS];
    #pragma unroll
    for (int r = 0; r < ZROWS; ++r) acc[r] = 0.f;
    #pragma unroll 4
    for (int e = 0; e < DD_; ++e) {
        float w = g_WT[e * DD_ + tid];
        float4 a0 = *(const float4*)&xst[e][0];
        float4 a1 = *(const float4*)&xst[e][4];
        float4 a2 = *(const float4*)&xst[e][8];
        float4 a3 = *(const float4*)&xst[e][12];
        acc[0]  += a0.x * w;  acc[1]  += a0.y * w;  acc[2]  += a0.z * w;  acc[3]  += a0.w * w;
        acc[4]  += a1.x * w;  acc[5]  += a1.y * w;  acc[6]  += a1.z * w;  acc[7]  += a1.w * w;
        acc[8]  += a2.x * w;  acc[9]  += a2.y * w;  acc[10] += a2.z * w;  acc[11] += a2.w * w;
        acc[12] += a3.x * w;  acc[13] += a3.y * w;  acc[14] += a3.z * w;  acc[15] += a3.w * w;
    }

    int nt = tid >> 3;
    int lbase = (tid & 7) * 4;
    #pragma unroll
    for (int r = 0; r < ZROWS; ++r) {
        int i = i0 + r;
        float zv = 0.f;
        if (i < NN_) {
            zv = g_dinv[i] * acc[r];
            g_z[(size_t)i * DD_ + tid] = zv;
        }
        float zh = hi13(zv), zl = zv - zh;
        int rc = i & 31;
        int ks = rc >> 3, kk = rc & 7;
        int b = kk >> 2;
        int lane = lbase + (kk & 3);
        size_t o = (size_t)(i >> 5) * 8192 + (size_t)((nt * 4 + ks) * 64 + lane * 2 + b);
        g_zfrag[o]        = zh;
        g_zfrag[o + 4096] = zl;
    }
}

// ---------------- K3: persistent mma.sync tf32x3 GEMM ----------------
// U[j,d] = sum_i motif[i,j] * z[i,d]
// SMEM per stage: A frags 32KB ([term][mt8][ks4][lane32][4]f), B frags 32KB
#define STAGE_BYTES 65536
#define GEMM_SMEM   (2 * STAGE_BYTES)

__device__ __forceinline__ float ldm(const float* __restrict__ m, int i, int j) {
    return (i < NN_ && j < NN_) ? __ldg(&m[(size_t)i * NN_ + j]) : 0.f;
}

__device__ __forceinline__ void prefetchA(float* apre, const float* __restrict__ motif,
                                          int ic, int J0, int w, int row, int cb) {
    int j = J0 + w * 16 + row;
    int ib = ic * 32 + cb;
    #pragma unroll
    for (int ks = 0; ks < 4; ++ks) {
        int i = ib + ks * 8;
        apre[ks * 4 + 0] = ldm(motif, i,     j);
        apre[ks * 4 + 1] = ldm(motif, i,     j + 8);
        apre[ks * 4 + 2] = ldm(motif, i + 4, j);
        apre[ks * 4 + 3] = ldm(motif, i + 4, j + 8);
    }
}

__global__ __launch_bounds__(256, 1) void k_gemm_mma(const float* __restrict__ motif) {
    extern __shared__ char sm[];
    int tid = threadIdx.x;
    int w = tid >> 5, l = tid & 31;
    int wm = w & 1, wn = w >> 1;
    int row = l >> 2, cb = l & 3;

    for (int u = blockIdx.x; u < NUNITS; u += GRID_GEMM) {
        int jt = u % NJT, ksp = u / NJT;
        int J0 = jt * 128;
        int c0 = (ksp * NCHUNK) / KSPL;
        int c1 = ((ksp + 1) * NCHUNK) / KSPL;
        int nch = c1 - c0;

        float4 acc[4][4];
        #pragma unroll
        for (int a = 0; a < 4; ++a)
            #pragma unroll
            for (int b = 0; b < 4; ++b) acc[a][b] = make_float4(0.f, 0.f, 0.f, 0.f);

        float apre[16];
        prefetchA(apre, motif, c0, J0, w, row, cb);
        {   // cp.async B chunk c0 -> stage 0
            const float* src = g_zfrag + (size_t)c0 * 8192;
            char* Bs = sm + 32768;
            #pragma unroll
            for (int q = 0; q < 8; ++q)
                cp16(Bs + (tid + q * 256) * 16, src + (size_t)(tid + q * 256) * 4);
            cp_commit();
        }

        for (int cc = 0; cc < nch; ++cc) {
            int s = cc & 1;
            char* As = sm + s * STAGE_BYTES;
            char* Bs = As + 32768;

            // STS A(cc) fragments (hi/lo split)
            #pragma unroll
            for (int ks = 0; ks < 4; ++ks) {
                float4 hi, lo;
                float v0 = apre[ks * 4 + 0], v1 = apre[ks * 4 + 1];
                float v2 = apre[ks * 4 + 2], v3 = apre[ks * 4 + 3];
                hi.x = hi13(v0); lo.x = v0 - hi.x;
                hi.y = hi13(v1); lo.y = v1 - hi.y;
                hi.z = hi13(v2); lo.z = v2 - hi.z;
                hi.w = hi13(v3); lo.w = v3 - hi.w;
                *(float4*)(As +         (w * 4 + ks) * 512 + l * 16) = hi;
                *(float4*)(As + 16384 + (w * 4 + ks) * 512 + l * 16) = lo;
            }

            if (cc + 1 < nch) {
                prefetchA(apre, motif, c0 + cc + 1, J0, w, row, cb);
                const float* src = g_zfrag + (size_t)(c0 + cc + 1) * 8192;
                char* Bn = sm + (s ^ 1) * STAGE_BYTES + 32768;
                #pragma unroll
                for (int q = 0; q < 8; ++q)
                    cp16(Bn + (tid + q * 256) * 16, src + (size_t)(tid + q * 256) * 4);
                cp_commit();
                cp_wait<1>();
            } else {
                cp_wait<0>();
            }
            __syncthreads();

            // MMA over this chunk: 4 k-steps x 4x4 tiles x 3 split terms
            #pragma unroll
            for (int ks = 0; ks < 4; ++ks) {
                float2 bh[4], bl[4];
                float4 ah[4], al[4];
                #pragma unroll
                for (int ntl = 0; ntl < 4; ++ntl) {
                    int bo = ((wn * 4 + ntl) * 4 + ks) * 256 + l * 8;
                    bh[ntl] = *(const float2*)(Bs + bo);
                    bl[ntl] = *(const float2*)(Bs + 16384 + bo);
                }
                #pragma unroll
                for (int mtl = 0; mtl < 4; ++mtl) {
                    int ao = ((wm * 4 + mtl) * 4 + ks) * 512 + l * 16;
                    ah[mtl] = *(const float4*)(As + ao);
                    al[mtl] = *(const float4*)(As + 16384 + ao);
                }
                #pragma unroll
                for (int mtl = 0; mtl < 4; ++mtl)
                    #pragma unroll
                    for (int ntl = 0; ntl < 4; ++ntl) {
                        mma8(acc[mtl][ntl], ah[mtl], bh[ntl]);
                        mma8(acc[mtl][ntl], ah[mtl], bl[ntl]);
                        mma8(acc[mtl][ntl], al[mtl], bh[ntl]);
                    }
            }
            __syncthreads();
        }

        // epilogue: write partials
        float* Up = g_Upart[ksp];
        #pragma unroll
        for (int mtl = 0; mtl < 4; ++mtl) {
            int r0 = J0 + wm * 64 + mtl * 16 + row;
            #pragma unroll
            for (int ntl = 0; ntl < 4; ++ntl) {
                int d0 = wn * 32 + ntl * 8 + cb * 2;
                float4 a = acc[mtl][ntl];
                if (r0 < NN_)     *(float2*)&Up[(size_t)r0 * 128 + d0]       = make_float2(a.x, a.y);
                if (r0 + 8 < NN_) *(float2*)&Up[(size_t)(r0 + 8) * 128 + d0] = make_float2(a.z, a.w);
            }
        }
        __syncthreads();
    }
}

// ---------------- K4: epilogue — h = tanh(dinv*(U+z)+b), scores ----------------
__global__ __launch_bounds__(256) void k_epi(const float* __restrict__ b_gcn,
                                             const float* __restrict__ w_score,
                                             const float* __restrict__ b_score,
                                             float* __restrict__ out_scores) {
    int warp = threadIdx.x >> 5;
    int lane = threadIdx.x & 31;
    int j = blockIdx.x * 8 + warp;
    if (j >= NN_) return;
    float dj = g_dinv[j];
    float ssum = 0.f;
    #pragma unroll
    for (int q = 0; q < 4; ++q) {
        int d = lane + 32 * q;
        size_t off = (size_t)j * DD_ + d;
        float u = 0.f;
        #pragma unroll
        for (int s = 0; s < KSPL; ++s) u += g_Upart[s][off];
        u += g_z[off];
        float hh = tanhf(dj * u + b_gcn[d]);
        g_h[off] = hh;
        ssum += hh * w_score[d];
    }
    #pragma unroll
    for (int o = 16; o; o >>= 1) ssum += __shfl_down_sync(0xffffffffu, ssum, o);
    if (lane == 0) {
        float sc = ssum + b_score[0];
        g_scores[j] = sc;
        out_scores[j] = sc;
    }
}

// ---------------- K5: exact top-k selection ----------------
__global__ __launch_bounds__(1024) void k_select(float* __restrict__ out_topidx_f) {
    __shared__ unsigned keys[NN_];
    __shared__ unsigned hist[256];
    __shared__ unsigned sc[1024];
    __shared__ unsigned sh_prefix, sh_r, sh_cg;
    int tid = threadIdx.x;

    for (int i = tid; i < NN_; i += 1024) {
        unsigned u = __float_as_uint(g_scores[i]);
        u = (u & 0x80000000u) ? ~u : (u | 0x80000000u);
        keys[i] = u;
    }
    if (tid == 0) { sh_prefix = 0u; sh_r = KSEL; sh_cg = 0u; }
    __syncthreads();

    for (int p = 3; p >= 0; --p) {
        if (tid < 256) hist[tid] = 0u;
        __syncthreads();
        unsigned msk  = (p == 3) ? 0u : (0xFFFFFFFFu << (8 * (p + 1)));
        unsigned pref = sh_prefix;
        for (int i = tid; i < NN_; i += 1024) {
            unsigned kk = keys[i];
            if ((kk & msk) == pref) atomicAdd(&hist[(kk >> (8 * p)) & 255], 1u);
        }
        __syncthreads();
        if (tid == 0) {
            unsigned r = sh_r, c = 0; int b = 0;
            for (b = 255; b >= 0; --b) {
                if (c + hist[b] >= r) break;
                c += hist[b];
            }
            sh_r = r - c;
            sh_prefix = pref | ((unsigned)b << (8 * p));
        }
        __syncthreads();
    }
    unsigned T = sh_prefix;

    {
        unsigned c = 0;
        for (int i = tid; i < NN_; i += 1024) c += (keys[i] > T);
        atomicAdd(&sh_cg, c);
    }
    __syncthreads();
    unsigned ties_needed = KSEL - sh_cg;

    int base = tid * 10;
    int end  = base + 10; if (end > NN_) end = NN_;
    if (base > NN_) base = NN_;

    unsigned tc = 0;
    for (int i = base; i < end; ++i) tc += (keys[i] == T);
    sc[tid] = tc; __syncthreads();
    for (int off = 1; off < 1024; off <<= 1) {
        unsigned v = (tid >= off) ? sc[tid - off] : 0u;
        __syncthreads(); sc[tid] += v; __syncthreads();
    }
    unsigned tie_excl = sc[tid] - tc;
    __syncthreads();

    unsigned scnt = 0;
    {
        unsigned tr = tie_excl;
        for (int i = base; i < end; ++i) {
            unsigned kk = keys[i];
            bool tie = (kk == T);
            bool sel = (kk > T) || (tie && tr < ties_needed);
            tr += tie; scnt += sel;
        }
    }
    sc[tid] = scnt; __syncthreads();
    for (int off = 1; off < 1024; off <<= 1) {
        unsigned v = (tid >= off) ? sc[tid - off] : 0u;
        __syncthreads(); sc[tid] += v; __syncthreads();
    }
    unsigned pos = sc[tid] - scnt;
    {
        unsigned tr = tie_excl;
        for (int i = base; i < end; ++i) {
            unsigned kk = keys[i];
            bool tie = (kk == T);
            bool sel = (kk > T) || (tie && tr < ties_needed);
            tr += tie;
            if (sel) {
                g_topidx[pos] = i;
                out_topidx_f[pos] = (float)i;
                ++pos;
            }
        }
    }
}

// ---------------- K6: x_pool gather (float4) ----------------
__global__ void k_xpool(float* __restrict__ out_x) {
    int t = blockIdx.x * 256 + threadIdx.x;      // one float4 per thread
    if (t >= KSEL * DD_ / 4) return;
    int r  = t >> 5;                              // 32 float4 per row
    int d4 = (t & 31) * 4;
    float4 v = *(const float4*)&g_h[(size_t)g_topidx[r] * DD_ + d4];
    *(float4*)&out_x[(size_t)r * DD_ + d4] = v;
}

// ---------------- K7: adjacency_pool & motif_pool gathers (4 c's / thread) ----------------
__global__ __launch_bounds__(256) void k_pool(const float* __restrict__ adjacency,
                                              const float* __restrict__ motif,
                                              float* __restrict__ out_adj,
                                              float* __restrict__ out_motif) {
    int r = blockIdx.y;
    int c0 = (blockIdx.x * 256 + threadIdx.x) * 4;
    if (c0 >= KSEL) return;
    int ri = g_topidx[r];
    size_t rb = (size_t)ri * NN_;
    int ci0 = g_topidx[c0], ci1 = g_topidx[c0 + 1], ci2 = g_topidx[c0 + 2], ci3 = g_topidx[c0 + 3];
    float4 va, vm;
    va.x = __ldg(&adjacency[rb + ci0]);  vm.x = __ldg(&motif[rb + ci0]);
    va.y = __ldg(&adjacency[rb + ci1]);  vm.y = __ldg(&motif[rb + ci1]);
    va.z = __ldg(&adjacency[rb + ci2]);  vm.z = __ldg(&motif[rb + ci2]);
    va.w = __ldg(&adjacency[rb + ci3]);  vm.w = __ldg(&motif[rb + ci3]);
    size_t dst = (size_t)r * KSEL + c0;
    *(float4*)&out_adj[dst]   = va;
    *(float4*)&out_motif[dst] = vm;
}

// ---------------- launch ----------------
extern "C" void kernel_launch(void* const* d_in, const int* in_sizes, int n_in,
                              void* d_out, int out_size) {
    const float* x       = (const float*)d_in[0];
    const float* adj     = (const float*)d_in[1];
    const float* motif   = (const float*)d_in[2];
    const float* W_gcn   = (const float*)d_in[3];
    const float* b_gcn   = (const float*)d_in[4];
    const float* w_score = (const float*)d_in[5];
    const float* b_score = (const float*)d_in[6];
    float* out = (float*)d_out;

    float* out_x      = out + OFF_XPOOL;
    float* out_adj    = out + OFF_ADJ;
    float* out_motif  = out + OFF_MOTIF;
    float* out_scores = out + OFF_SCORES;
    float* out_tif    = out + OFF_TOPIDX;

    cudaFuncSetAttribute(k_gemm_mma, cudaFuncAttributeMaxDynamicSharedMemorySize, GEMM_SMEM);

    k_transW<<<16, 1024>>>(W_gcn);
    k_deg_part<<<dim3(40, DEG_CHUNKS), 256>>>(motif);
    k_deg_fin<<<40, 256>>>();
    k_z<<<625, 128>>>(x);
    k_gemm_mma<<<GRID_GEMM, 256, GEMM_SMEM>>>(motif);
    k_epi<<<1250, 256>>>(b_gcn, w_score, b_score, out_scores);
    k_select<<<1, 1024>>>(out_tif);
    k_xpool<<<625, 256>>>(out_x);
    k_pool<<<dim3(5, KSEL), 256>>>(adj, motif, out_adj, out_motif);
}

// round 10
// speedup vs baseline: 1.5723x; 1.2165x over previous
#include <cuda_runtime.h>
#include <cuda_bf16.h>
#include <cuda_fp16.h>
#include <math.h>
#include <stdint.h>

// Problem constants
#define NN_ 10000
#define DD_ 128
#define KSEL 5000

// GEMM config
#define NJT 79              // j tiles of 128
#define KSPL 16             // k splits
#define NUNITS (NJT * KSPL) // 1264
#define NCHUNK 313          // 32-i chunks covering 10016
#define GRID_GEMM 148
#define ZSCALE 2048.0f
#define INV_ZSCALE (1.0f / 2048.0f)

// deg partials
#define DEG_CHUNKS 16
#define DEG_ROWS   625

// Output layout (float32, reference return order)
#define OFF_XPOOL   ((size_t)0)
#define OFF_ADJ     ((size_t)KSEL * DD_)
#define OFF_MOTIF   (OFF_ADJ + (size_t)KSEL * KSEL)
#define OFF_SCORES  (OFF_MOTIF + (size_t)KSEL * KSEL)
#define OFF_TOPIDX  (OFF_SCORES + (size_t)NN_)

// ---------------- device scratch ----------------
__device__ float g_WT[DD_ * DD_];
__device__ float g_part[DEG_CHUNKS * NN_];
__device__ float g_dinv[NN_];
__device__ float g_z[(size_t)NN_ * DD_];            // plain layout (epilogue +I term)
__device__ uint4 g_zfrag[(size_t)NCHUNK * 1024];    // fp16 fragment layout hi/lo (~5MB)
__device__ float g_Upart[KSPL][(size_t)NN_ * DD_];  // split-K partials
__device__ float g_h[(size_t)NN_ * DD_];
__device__ float g_scores[NN_];
__device__ int   g_topidx[KSEL];

// ---------------- helpers ----------------
__device__ __forceinline__ void cp16(void* smem, const void* gmem) {
    unsigned a = (unsigned)__cvta_generic_to_shared(smem);
    asm volatile("cp.async.ca.shared.global [%0], [%1], 16;\n" :: "r"(a), "l"(gmem) : "memory");
}
__device__ __forceinline__ void cp_commit() {
    asm volatile("cp.async.commit_group;\n" ::: "memory");
}
template<int NPEND>
__device__ __forceinline__ void cp_wait() {
    asm volatile("cp.async.wait_group %0;\n" :: "n"(NPEND) : "memory");
}
__device__ __forceinline__ uint32_t pack2h(__half a, __half b) {
    return (uint32_t)__half_as_ushort(a) | ((uint32_t)__half_as_ushort(b) << 16);
}
// D(16x8,f32) += A(16x16,f16) * B(16x8,f16)
__device__ __forceinline__ void mma16(float4& d, const uint4& a, const uint2& b) {
    asm volatile(
        "mma.sync.aligned.m16n8k16.row.col.f32.f16.f16.f32 "
        "{%0,%1,%2,%3}, {%4,%5,%6,%7}, {%8,%9}, {%0,%1,%2,%3};\n"
        : "+f"(d.x), "+f"(d.y), "+f"(d.z), "+f"(d.w)
        : "r"(a.x), "r"(a.y), "r"(a.z), "r"(a.w), "r"(b.x), "r"(b.y));
}

// ---------------- K0: W transpose ----------------
__global__ void k_transW(const float* __restrict__ W) {
    int t = blockIdx.x * blockDim.x + threadIdx.x;
    if (t < DD_ * DD_) {
        int e = t >> 7, d = t & 127;
        g_WT[e * DD_ + d] = W[d * DD_ + e];
    }
}

// ---------------- K1: deg column sums ----------------
__global__ void k_deg_part(const float* __restrict__ motif) {
    int j = blockIdx.x * 256 + threadIdx.x;
    int c = blockIdx.y;
    if (j >= NN_) return;
    int i0 = c * DEG_ROWS, i1 = i0 + DEG_ROWS;
    float s0 = 0.f, s1 = 0.f, s2 = 0.f, s3 = 0.f;
    int i = i0;
    for (; i + 4 <= i1; i += 4) {
        s0 += motif[(size_t)(i    ) * NN_ + j];
        s1 += motif[(size_t)(i + 1) * NN_ + j];
        s2 += motif[(size_t)(i + 2) * NN_ + j];
        s3 += motif[(size_t)(i + 3) * NN_ + j];
    }
    for (; i < i1; ++i) s0 += motif[(size_t)i * NN_ + j];
    g_part[c * NN_ + j] = (s0 + s1) + (s2 + s3);
}

__global__ void k_deg_fin() {
    int j = blockIdx.x * 256 + threadIdx.x;
    if (j >= NN_) return;
    float d = 1.0f;
    #pragma unroll
    for (int c = 0; c < DEG_CHUNKS; ++c) d += g_part[c * NN_ + j];
    g_dinv[j] = 1.0f / sqrtf(d);
}

// ---------------- K2: z = dinv*(x@W^T); emit plain + fp16 fragment hi/lo ----------------
// Per 32-i chunk, zfrag half layout: [term2][nt16][ks2][lane32][reg2][h2]
//   (element i,d: kk=i&15, ks=(i>>4)&1, nt=d>>3, lane=(d&7)*4+((kk&7)>>1), reg=kk>>3, h=kk&1)
// Each block does 16 rows = one ks. Fragments staged in SMEM, written out coalesced.
#define ZROWS 16
#define KZ_SMEM ((16384 + 2560 + 2048) * 4)
__global__ __launch_bounds__(128) void k_z(const float* __restrict__ x) {
    extern __shared__ float zdyn[];
    float* wsm = zdyn;                                  // 16384 f (WT)
    float (*xst)[20] = (float(*)[20])(zdyn + 16384);    // [128][20]
    __half* zf = (__half*)(zdyn + 16384 + 2560);        // 4096 halves staging

    int i0 = blockIdx.x * ZROWS;
    int tid = threadIdx.x;                              // = d

    // stage WT in smem via cp.async
    #pragma unroll 8
    for (int q = 0; q < 32; ++q) {
        int cid = tid + q * 128;
        cp16(wsm + cid * 4, g_WT + cid * 4);
    }
    cp_commit();
    for (int l = tid; l < ZROWS * DD_; l += 128) {
        int r = l >> 7, e = l & 127;
        xst[e][r] = (i0 + r < NN_) ? x[(size_t)(i0 + r) * DD_ + e] : 0.f;
    }
    cp_wait<0>();
    __syncthreads();

    float acc[ZROWS];
    #pragma unroll
    for (int r = 0; r < ZROWS; ++r) acc[r] = 0.f;
    #pragma unroll 4
    for (int e = 0; e < DD_; ++e) {
        float w = wsm[e * DD_ + tid];
        float4 a0 = *(const float4*)&xst[e][0];
        float4 a1 = *(const float4*)&xst[e][4];
        float4 a2 = *(const float4*)&xst[e][8];
        float4 a3 = *(const float4*)&xst[e][12];
        acc[0]  += a0.x * w;  acc[1]  += a0.y * w;  acc[2]  += a0.z * w;  acc[3]  += a0.w * w;
        acc[4]  += a1.x * w;  acc[5]  += a1.y * w;  acc[6]  += a1.z * w;  acc[7]  += a1.w * w;
        acc[8]  += a2.x * w;  acc[9]  += a2.y * w;  acc[10] += a2.z * w;  acc[11] += a2.w * w;
        acc[12] += a3.x * w;  acc[13] += a3.y * w;  acc[14] += a3.z * w;  acc[15] += a3.w * w;
    }

    // stage fragments in smem: zf[term][nt16][lane32][reg2][h2] (ks fixed per block)
    int nt = tid >> 3, nc = tid & 7;
    #pragma unroll
    for (int r = 0; r < ZROWS; ++r) {
        int i = i0 + r;
        float Z = 0.f;
        if (i < NN_) {
            float zv = g_dinv[i] * acc[r];
            g_z[(size_t)i * DD_ + tid] = zv;
            Z = zv * ZSCALE;
        }
        __half zh = __float2half_rn(Z);
        __half zl = __float2half_rn(Z - __half2float(zh));
        int kk = i & 15;
        int lane = nc * 4 + ((kk & 7) >> 1);
        int reg = kk >> 3, h = kk & 1;
        int off = nt * 128 + lane * 4 + reg * 2 + h;
        zf[off]        = zh;
        zf[off + 2048] = zl;
    }
    __syncthreads();

    // coalesced writeout: 512 uint4 -> global [term][nt][ks][...]
    int ks = blockIdx.x & 1;
    int chunk = i0 >> 5;
    const uint4* zsrc = (const uint4*)zf;
    #pragma unroll
    for (int q = 0; q < 4; ++q) {
        int idx = tid + q * 128;          // 0..511
        int region = idx >> 4;            // term*16 + nt
        int part = idx & 15;
        g_zfrag[(size_t)chunk * 1024 + (region * 2 + ks) * 16 + part] = zsrc[idx];
    }
}

// ---------------- K3: persistent mma.sync fp16x3 GEMM ----------------
// U[j,d] = sum_i motif[i,j] * z[i,d]   (z pre-scaled by 2048; rescaled at store)
// SMEM per stage 32KB: A halves 16KB [term][mt8][ks2][lane32][8h], B halves 16KB [term][nt16][ks2][lane32][4h]
#define STAGE_BYTES 32768
#define GEMM_SMEM   (2 * STAGE_BYTES)

__device__ __forceinline__ float ldm(const float* __restrict__ m, int i, int j) {
    return (i < NN_ && j < NN_) ? __ldg(&m[(size_t)i * NN_ + j]) : 0.f;
}

// fragment-order A prefetch: per ks 8 halves (a0..a7): (g,c0),(g,c0+1),(g+8,c0),(g+8,c0+1),
// (g,c0+8),(g,c0+9),(g+8,c0+8),(g+8,c0+9) with j=m-row, i=k
__device__ __forceinline__ void prefetchA(float* apre, const float* __restrict__ motif,
                                          int ic, int J0, int w, int g, int c0) {
    int jb = J0 + w * 16 + g;
    #pragma unroll
    for (int ks = 0; ks < 2; ++ks) {
        int ib = ic * 32 + ks * 16 + c0;
        apre[ks * 8 + 0] = ldm(motif, ib,     jb);
        apre[ks * 8 + 1] = ldm(motif, ib + 1, jb);
        apre[ks * 8 + 2] = ldm(motif, ib,     jb + 8);
        apre[ks * 8 + 3] = ldm(motif, ib + 1, jb + 8);
        apre[ks * 8 + 4] = ldm(motif, ib + 8, jb);
        apre[ks * 8 + 5] = ldm(motif, ib + 9, jb);
        apre[ks * 8 + 6] = ldm(motif, ib + 8, jb + 8);
        apre[ks * 8 + 7] = ldm(motif, ib + 9, jb + 8);
    }
}

__global__ __launch_bounds__(256, 1) void k_gemm_mma(const float* __restrict__ motif) {
    extern __shared__ char sm[];
    int tid = threadIdx.x;
    int w = tid >> 5, l = tid & 31;
    int wm = w & 1, wn = w >> 1;
    int g = l >> 2, cb = l & 3;
    int c0 = cb * 2;

    for (int u = blockIdx.x; u < NUNITS; u += GRID_GEMM) {
        int jt = u % NJT, ksp = u / NJT;
        int J0 = jt * 128;
        int ch0 = (ksp * NCHUNK) / KSPL;
        int ch1 = ((ksp + 1) * NCHUNK) / KSPL;
        int nch = ch1 - ch0;

        float4 acc[4][4];
        #pragma unroll
        for (int a = 0; a < 4; ++a)
            #pragma unroll
            for (int b = 0; b < 4; ++b) acc[a][b] = make_float4(0.f, 0.f, 0.f, 0.f);

        float apre[16];
        prefetchA(apre, motif, ch0, J0, w, g, c0);
        {   // cp.async B chunk ch0 -> stage 0 (16 KB)
            const char* src = (const char*)g_zfrag + (size_t)ch0 * 16384;
            char* Bs = sm + 16384;
            #pragma unroll
            for (int q = 0; q < 4; ++q)
                cp16(Bs + (tid + q * 256) * 16, src + (size_t)(tid + q * 256) * 16);
            cp_commit();
        }

        for (int cc = 0; cc < nch; ++cc) {
            int s = cc & 1;
            char* As = sm + s * STAGE_BYTES;
            char* Bs = As + 16384;

            // STS A(cc) fragments (hi/lo fp16 split), mt = w
            #pragma unroll
            for (int ks = 0; ks < 2; ++ks) {
                uint32_t ph[4], pl[4];
                #pragma unroll
                for (int q = 0; q < 4; ++q) {
                    float v0 = apre[ks * 8 + q * 2], v1 = apre[ks * 8 + q * 2 + 1];
                    __half h0 = __float2half_rn(v0);
                    __half h1 = __float2half_rn(v1);
                    __half l0 = __float2half_rn(v0 - __half2float(h0));
                    __half l1 = __float2half_rn(v1 - __half2float(h1));
                    ph[q] = pack2h(h0, h1);
                    pl[q] = pack2h(l0, l1);
                }
                *(uint4*)(As +        (w * 2 + ks) * 512 + l * 16) = make_uint4(ph[0], ph[1], ph[2], ph[3]);
                *(uint4*)(As + 8192 + (w * 2 + ks) * 512 + l * 16) = make_uint4(pl[0], pl[1], pl[2], pl[3]);
            }

            if (cc + 1 < nch) {
                prefetchA(apre, motif, ch0 + cc + 1, J0, w, g, c0);
                const char* src = (const char*)g_zfrag + (size_t)(ch0 + cc + 1) * 16384;
                char* Bn = sm + (s ^ 1) * STAGE_BYTES + 16384;
                #pragma unroll
                for (int q = 0; q < 4; ++q)
                    cp16(Bn + (tid + q * 256) * 16, src + (size_t)(tid + q * 256) * 16);
                cp_commit();
                cp_wait<1>();
            } else {
                cp_wait<0>();
            }
            __syncthreads();

            // MMA: 2 k-steps x (4x4 tiles) x 3 split terms
            #pragma unroll
            for (int ks = 0; ks < 2; ++ks) {
                uint2 bh[4], bl[4];
                uint4 ah[4], al[4];
                #pragma unroll
                for (int ntl = 0; ntl < 4; ++ntl) {
                    int nto = ((wn * 4 + ntl) * 2 + ks) * 256 + l * 8;
                    bh[ntl] = *(const uint2*)(Bs + nto);
                    bl[ntl] = *(const uint2*)(Bs + 8192 + nto);
                }
                #pragma unroll
                for (int mtl = 0; mtl < 4; ++mtl) {
                    int mto = ((wm * 4 + mtl) * 2 + ks) * 512 + l * 16;
                    ah[mtl] = *(const uint4*)(As + mto);
                    al[mtl] = *(const uint4*)(As + 8192 + mto);
                }
                #pragma unroll
                for (int mtl = 0; mtl < 4; ++mtl)
                    #pragma unroll
                    for (int ntl = 0; ntl < 4; ++ntl) {
                        mma16(acc[mtl][ntl], ah[mtl], bh[ntl]);
                        mma16(acc[mtl][ntl], ah[mtl], bl[ntl]);
                        mma16(acc[mtl][ntl], al[mtl], bh[ntl]);
                    }
            }
            __syncthreads();
        }

        // epilogue: write partials (rescale by 1/2048)
        float* Up = g_Upart[ksp];
        #pragma unroll
        for (int mtl = 0; mtl < 4; ++mtl) {
            int r0 = J0 + wm * 64 + mtl * 16 + g;
            #pragma unroll
            for (int ntl = 0; ntl < 4; ++ntl) {
                int d0 = wn * 32 + ntl * 8 + cb * 2;
                float4 a = acc[mtl][ntl];
                if (r0 < NN_)
                    *(float2*)&Up[(size_t)r0 * 128 + d0] =
                        make_float2(a.x * INV_ZSCALE, a.y * INV_ZSCALE);
                if (r0 + 8 < NN_)
                    *(float2*)&Up[(size_t)(r0 + 8) * 128 + d0] =
                        make_float2(a.z * INV_ZSCALE, a.w * INV_ZSCALE);
            }
        }
        __syncthreads();
    }
}

// ---------------- K4: epilogue — h = tanh(dinv*(U+z)+b), scores ----------------
__global__ __launch_bounds__(256) void k_epi(const float* __restrict__ b_gcn,
                                             const float* __restrict__ w_score,
                                             const float* __restrict__ b_score,
                                             float* __restrict__ out_scores) {
    int warp = threadIdx.x >> 5;
    int lane = threadIdx.x & 31;
    int j = blockIdx.x * 8 + warp;
    if (j >= NN_) return;
    float dj = g_dinv[j];
    float ssum = 0.f;
    #pragma unroll
    for (int q = 0; q < 4; ++q) {
        int d = lane + 32 * q;
        size_t off = (size_t)j * DD_ + d;
        float u = 0.f;
        #pragma unroll
        for (int s = 0; s < KSPL; ++s) u += g_Upart[s][off];
        u += g_z[off];
        float hh = tanhf(dj * u + b_gcn[d]);
        g_h[off] = hh;
        ssum += hh * w_score[d];
    }
    #pragma unroll
    for (int o = 16; o; o >>= 1) ssum += __shfl_down_sync(0xffffffffu, ssum, o);
    if (lane == 0) {
        float sc = ssum + b_score[0];
        g_scores[j] = sc;
        out_scores[j] = sc;
    }
}

// ---------------- K5: exact top-k selection ----------------
__global__ __launch_bounds__(1024) void k_select(float* __restrict__ out_topidx_f) {
    __shared__ unsigned keys[NN_];
    __shared__ unsigned hist[256];
    __shared__ unsigned sc[1024];
    __shared__ unsigned sh_prefix, sh_r, sh_cg;
    int tid = threadIdx.x;

    for (int i = tid; i < NN_; i += 1024) {
        unsigned u = __float_as_uint(g_scores[i]);
        u = (u & 0x80000000u) ? ~u : (u | 0x80000000u);
        keys[i] = u;
    }
    if (tid == 0) { sh_prefix = 0u; sh_r = KSEL; sh_cg = 0u; }
    __syncthreads();

    for (int p = 3; p >= 0; --p) {
        if (tid < 256) hist[tid] = 0u;
        __syncthreads();
        unsigned msk  = (p == 3) ? 0u : (0xFFFFFFFFu << (8 * (p + 1)));
        unsigned pref = sh_prefix;
        for (int i = tid; i < NN_; i += 1024) {
            unsigned kk = keys[i];
            if ((kk & msk) == pref) atomicAdd(&hist[(kk >> (8 * p)) & 255], 1u);
        }
        __syncthreads();
        if (tid == 0) {
            unsigned r = sh_r, c = 0; int b = 0;
            for (b = 255; b >= 0; --b) {
                if (c + hist[b] >= r) break;
                c += hist[b];
            }
            sh_r = r - c;
            sh_prefix = pref | ((unsigned)b << (8 * p));
        }
        __syncthreads();
    }
    unsigned T = sh_prefix;

    {
        unsigned c = 0;
        for (int i = tid; i < NN_; i += 1024) c += (keys[i] > T);
        atomicAdd(&sh_cg, c);
    }
    __syncthreads();
    unsigned ties_needed = KSEL - sh_cg;

    int base = tid * 10;
    int end  = base + 10; if (end > NN_) end = NN_;
    if (base > NN_) base = NN_;

    unsigned tc = 0;
    for (int i = base; i < end; ++i) tc += (keys[i] == T);
    sc[tid] = tc; __syncthreads();
    for (int off = 1; off < 1024; off <<= 1) {
        unsigned v = (tid >= off) ? sc[tid - off] : 0u;
        __syncthreads(); sc[tid] += v; __syncthreads();
    }
    unsigned tie_excl = sc[tid] - tc;
    __syncthreads();

    unsigned scnt = 0;
    {
        unsigned tr = tie_excl;
        for (int i = base; i < end; ++i) {
            unsigned kk = keys[i];
            bool tie = (kk == T);
            bool sel = (kk > T) || (tie && tr < ties_needed);
            tr += tie; scnt += sel;
        }
    }
    sc[tid] = scnt; __syncthreads();
    for (int off = 1; off < 1024; off <<= 1) {
        unsigned v = (tid >= off) ? sc[tid - off] : 0u;
        __syncthreads(); sc[tid] += v; __syncthreads();
    }
    unsigned pos = sc[tid] - scnt;
    {
        unsigned tr = tie_excl;
        for (int i = base; i < end; ++i) {
            unsigned kk = keys[i];
            bool tie = (kk == T);
            bool sel = (kk > T) || (tie && tr < ties_needed);
            tr += tie;
            if (sel) {
                g_topidx[pos] = i;
                out_topidx_f[pos] = (float)i;
                ++pos;
            }
        }
    }
}

// ---------------- K6: x_pool gather (float4) ----------------
__global__ void k_xpool(float* __restrict__ out_x) {
    int t = blockIdx.x * 256 + threadIdx.x;
    if (t >= KSEL * DD_ / 4) return;
    int r  = t >> 5;
    int d4 = (t & 31) * 4;
    float4 v = *(const float4*)&g_h[(size_t)g_topidx[r] * DD_ + d4];
    *(float4*)&out_x[(size_t)r * DD_ + d4] = v;
}

// ---------------- K7: adjacency_pool & motif_pool gathers (4 c's / thread) ----------------
__global__ __launch_bounds__(256) void k_pool(const float* __restrict__ adjacency,
                                              const float* __restrict__ motif,
                                              float* __restrict__ out_adj,
                                              float* __restrict__ out_motif) {
    int r = blockIdx.y;
    int c0 = (blockIdx.x * 256 + threadIdx.x) * 4;
    if (c0 >= KSEL) return;
    int ri = g_topidx[r];
    size_t rb = (size_t)ri * NN_;
    int ci0 = g_topidx[c0], ci1 = g_topidx[c0 + 1], ci2 = g_topidx[c0 + 2], ci3 = g_topidx[c0 + 3];
    float4 va, vm;
    va.x = __ldg(&adjacency[rb + ci0]);  vm.x = __ldg(&motif[rb + ci0]);
    va.y = __ldg(&adjacency[rb + ci1]);  vm.y = __ldg(&motif[rb + ci1]);
    va.z = __ldg(&adjacency[rb + ci2]);  vm.z = __ldg(&motif[rb + ci2]);
    va.w = __ldg(&adjacency[rb + ci3]);  vm.w = __ldg(&motif[rb + ci3]);
    size_t dst = (size_t)r * KSEL + c0;
    *(float4*)&out_adj[dst]   = va;
    *(float4*)&out_motif[dst] = vm;
}

// ---------------- launch ----------------
extern "C" void kernel_launch(void* const* d_in, const int* in_sizes, int n_in,
                              void* d_out, int out_size) {
    const float* x       = (const float*)d_in[0];
    const float* adj     = (const float*)d_in[1];
    const float* motif   = (const float*)d_in[2];
    const float* W_gcn   = (const float*)d_in[3];
    const float* b_gcn   = (const float*)d_in[4];
    const float* w_score = (const float*)d_in[5];
    const float* b_score = (const float*)d_in[6];
    float* out = (float*)d_out;

    float* out_x      = out + OFF_XPOOL;
    float* out_adj    = out + OFF_ADJ;
    float* out_motif  = out + OFF_MOTIF;
    float* out_scores = out + OFF_SCORES;
    float* out_tif    = out + OFF_TOPIDX;

    cudaFuncSetAttribute(k_gemm_mma, cudaFuncAttributeMaxDynamicSharedMemorySize, GEMM_SMEM);
    cudaFuncSetAttribute(k_z, cudaFuncAttributeMaxDynamicSharedMemorySize, KZ_SMEM);

    k_transW<<<16, 1024>>>(W_gcn);
    k_deg_part<<<dim3(40, DEG_CHUNKS), 256>>>(motif);
    k_deg_fin<<<40, 256>>>();
    k_z<<<626, 128, KZ_SMEM>>>(x);     // 626 blocks: last block zeroes chunk 312 upper half
    k_gemm_mma<<<GRID_GEMM, 256, GEMM_SMEM>>>(motif);
    k_epi<<<1250, 256>>>(b_gcn, w_score, b_score, out_scores);
    k_select<<<1, 1024>>>(out_tif);
    k_xpool<<<625, 256>>>(out_x);
    k_pool<<<dim3(5, KSEL), 256>>>(adj, motif, out_adj, out_motif);
}

// round 12
// speedup vs baseline: 1.6050x; 1.0208x over previous
#include <cuda_runtime.h>
#include <cuda_bf16.h>
#include <cuda_fp16.h>
#include <math.h>
#include <stdint.h>

// Problem constants
#define NN_ 10000
#define DD_ 128
#define KSEL 5000

// GEMM config
#define NJT 79              // j tiles of 128
#define KSPL 16             // k splits
#define NUNITS (NJT * KSPL) // 1264
#define NCHUNK 313          // 32-i chunks covering 10016
#define GRID_GEMM 148
#define ZSCALE 2048.0f
#define INV_ZSCALE (1.0f / 2048.0f)

// deg partials
#define DEG_CHUNKS 16
#define DEG_ROWS   625

// Output layout (float32, reference return order)
#define OFF_XPOOL   ((size_t)0)
#define OFF_ADJ     ((size_t)KSEL * DD_)
#define OFF_MOTIF   (OFF_ADJ + (size_t)KSEL * KSEL)
#define OFF_SCORES  (OFF_MOTIF + (size_t)KSEL * KSEL)
#define OFF_TOPIDX  (OFF_SCORES + (size_t)NN_)

// ---------------- device scratch ----------------
__device__ float g_WT[DD_ * DD_];
__device__ float g_part[DEG_CHUNKS * NN_];
__device__ float g_dinv[NN_];
__device__ float g_z[(size_t)NN_ * DD_];            // plain layout (epilogue +I term)
__device__ uint4 g_zfrag[(size_t)NCHUNK * 1024];    // fp16 fragment layout hi/lo (~5MB)
__device__ float g_Upart[KSPL][(size_t)NN_ * DD_];  // split-K partials
__device__ float g_h[(size_t)NN_ * DD_];
__device__ float g_scores[NN_];
__device__ int   g_topidx[KSEL];

// ---------------- helpers ----------------
__device__ __forceinline__ void cp16(void* smem, const void* gmem) {
    unsigned a = (unsigned)__cvta_generic_to_shared(smem);
    asm volatile("cp.async.ca.shared.global [%0], [%1], 16;\n" :: "r"(a), "l"(gmem) : "memory");
}
__device__ __forceinline__ void cp_commit() {
    asm volatile("cp.async.commit_group;\n" ::: "memory");
}
template<int NPEND>
__device__ __forceinline__ void cp_wait() {
    asm volatile("cp.async.wait_group %0;\n" :: "n"(NPEND) : "memory");
}
__device__ __forceinline__ uint32_t pack2h(__half a, __half b) {
    return (uint32_t)__half_as_ushort(a) | ((uint32_t)__half_as_ushort(b) << 16);
}
// D(16x8,f32) += A(16x16,f16) * B(16x8,f16)
__device__ __forceinline__ void mma16(float4& d, const uint4& a, const uint2& b) {
    asm volatile(
        "mma.sync.aligned.m16n8k16.row.col.f32.f16.f16.f32 "
        "{%0,%1,%2,%3}, {%4,%5,%6,%7}, {%8,%9}, {%0,%1,%2,%3};\n"
        : "+f"(d.x), "+f"(d.y), "+f"(d.z), "+f"(d.w)
        : "r"(a.x), "r"(a.y), "r"(a.z), "r"(a.w), "r"(b.x), "r"(b.y));
}

// ---------------- K0: W transpose ----------------
__global__ void k_transW(const float* __restrict__ W) {
    int t = blockIdx.x * blockDim.x + threadIdx.x;
    if (t < DD_ * DD_) {
        int e = t >> 7, d = t & 127;
        g_WT[e * DD_ + d] = W[d * DD_ + e];
    }
}

// ---------------- K1: deg column sums ----------------
__global__ void k_deg_part(const float* __restrict__ motif) {
    int j = blockIdx.x * 256 + threadIdx.x;
    int c = blockIdx.y;
    if (j >= NN_) return;
    int i0 = c * DEG_ROWS, i1 = i0 + DEG_ROWS;
    float s0 = 0.f, s1 = 0.f, s2 = 0.f, s3 = 0.f;
    int i = i0;
    for (; i + 4 <= i1; i += 4) {
        s0 += motif[(size_t)(i    ) * NN_ + j];
        s1 += motif[(size_t)(i + 1) * NN_ + j];
        s2 += motif[(size_t)(i + 2) * NN_ + j];
        s3 += motif[(size_t)(i + 3) * NN_ + j];
    }
    for (; i < i1; ++i) s0 += motif[(size_t)i * NN_ + j];
    g_part[c * NN_ + j] = (s0 + s1) + (s2 + s3);
}

__global__ void k_deg_fin() {
    int j = blockIdx.x * 256 + threadIdx.x;
    if (j >= NN_) return;
    float d = 1.0f;
    #pragma unroll
    for (int c = 0; c < DEG_CHUNKS; ++c) d += g_part[c * NN_ + j];
    g_dinv[j] = 1.0f / sqrtf(d);
}

// ---------------- K2: z = dinv*(x@W^T); emit plain + fp16 fragment hi/lo ----------------
// Per 32-i chunk, zfrag half layout: [term2][nt16][ks2][lane32][reg2][h2]
// Each block does 16 rows = one ks. Fragments staged in SMEM, written out coalesced.
// WT read directly from global (L2-resident) — NO smem staging (keeps occupancy high).
#define ZROWS 16
__global__ __launch_bounds__(128) void k_z(const float* __restrict__ x) {
    __shared__ float xst[DD_][20];       // [e][r], pad 20
    __shared__ __half zf[4096];          // fragment staging (8KB)

    int i0 = blockIdx.x * ZROWS;
    int tid = threadIdx.x;               // = d

    for (int l = tid; l < ZROWS * DD_; l += 128) {
        int r = l >> 7, e = l & 127;
        xst[e][r] = (i0 + r < NN_) ? x[(size_t)(i0 + r) * DD_ + e] : 0.f;
    }
    __syncthreads();

    float acc[ZROWS];
    #pragma unroll
    for (int r = 0; r < ZROWS; ++r) acc[r] = 0.f;
    #pragma unroll 4
    for (int e = 0; e < DD_; ++e) {
        float w = g_WT[e * DD_ + tid];
        float4 a0 = *(const float4*)&xst[e][0];
        float4 a1 = *(const float4*)&xst[e][4];
        float4 a2 = *(const float4*)&xst[e][8];
        float4 a3 = *(const float4*)&xst[e][12];
        acc[0]  += a0.x * w;  acc[1]  += a0.y * w;  acc[2]  += a0.z * w;  acc[3]  += a0.w * w;
        acc[4]  += a1.x * w;  acc[5]  += a1.y * w;  acc[6]  += a1.z * w;  acc[7]  += a1.w * w;
        acc[8]  += a2.x * w;  acc[9]  += a2.y * w;  acc[10] += a2.z * w;  acc[11] += a2.w * w;
        acc[12] += a3.x * w;  acc[13] += a3.y * w;  acc[14] += a3.z * w;  acc[15] += a3.w * w;
    }

    // stage fragments: zf[term][nt16][lane32][reg2][h2] (ks fixed per block)
    int nt = tid >> 3, nc = tid & 7;
    #pragma unroll
    for (int r = 0; r < ZROWS; ++r) {
        int i = i0 + r;
        float Z = 0.f;
        if (i < NN_) {
            float zv = g_dinv[i] * acc[r];
            g_z[(size_t)i * DD_ + tid] = zv;
            Z = zv * ZSCALE;
        }
        __half zh = __float2half_rn(Z);
        __half zl = __float2half_rn(Z - __half2float(zh));
        int kk = i & 15;
        int lane = nc * 4 + ((kk & 7) >> 1);
        int reg = kk >> 3, h = kk & 1;
        int off = nt * 128 + lane * 4 + reg * 2 + h;
        zf[off]        = zh;
        zf[off + 2048] = zl;
    }
    __syncthreads();

    // coalesced writeout: 512 uint4 -> global [term][nt][ks][...]
    int ks = blockIdx.x & 1;
    int chunk = i0 >> 5;
    const uint4* zsrc = (const uint4*)zf;
    #pragma unroll
    for (int q = 0; q < 4; ++q) {
        int idx = tid + q * 128;          // 0..511
        int region = idx >> 4;            // term*16 + nt
        int part = idx & 15;
        g_zfrag[(size_t)chunk * 1024 + (region * 2 + ks) * 16 + part] = zsrc[idx];
    }
}

// ---------------- K3: persistent mma.sync fp16x3 GEMM (3-stage, 1 sync/chunk) ----------------
// U[j,d] = sum_i motif[i,j] * z[i,d]   (z pre-scaled by 2048; rescaled at store)
// SMEM per stage 32KB: A halves 16KB, B halves 16KB
#define STAGE_BYTES 32768
#define NSTAGE 3
#define GEMM_SMEM   (NSTAGE * STAGE_BYTES)

__device__ __forceinline__ float ldm(const float* __restrict__ m, int i, int j) {
    return (i < NN_ && j < NN_) ? __ldg(&m[(size_t)i * NN_ + j]) : 0.f;
}

__device__ __forceinline__ void prefetchA(float* apre, const float* __restrict__ motif,
                                          int ic, int J0, int w, int g, int c0) {
    int jb = J0 + w * 16 + g;
    #pragma unroll
    for (int ks = 0; ks < 2; ++ks) {
        int ib = ic * 32 + ks * 16 + c0;
        apre[ks * 8 + 0] = ldm(motif, ib,     jb);
        apre[ks * 8 + 1] = ldm(motif, ib + 1, jb);
        apre[ks * 8 + 2] = ldm(motif, ib,     jb + 8);
        apre[ks * 8 + 3] = ldm(motif, ib + 1, jb + 8);
        apre[ks * 8 + 4] = ldm(motif, ib + 8, jb);
        apre[ks * 8 + 5] = ldm(motif, ib + 9, jb);
        apre[ks * 8 + 6] = ldm(motif, ib + 8, jb + 8);
        apre[ks * 8 + 7] = ldm(motif, ib + 9, jb + 8);
    }
}

__device__ __forceinline__ void stsA(char* As, const float* apre, int w, int l) {
    #pragma unroll
    for (int ks = 0; ks < 2; ++ks) {
        uint32_t ph[4], pl[4];
        #pragma unroll
        for (int q = 0; q < 4; ++q) {
            float v0 = apre[ks * 8 + q * 2], v1 = apre[ks * 8 + q * 2 + 1];
            __half h0 = __float2half_rn(v0);
            __half h1 = __float2half_rn(v1);
            __half l0 = __float2half_rn(v0 - __half2float(h0));
            __half l1 = __float2half_rn(v1 - __half2float(h1));
            ph[q] = pack2h(h0, h1);
            pl[q] = pack2h(l0, l1);
        }
        *(uint4*)(As +        (w * 2 + ks) * 512 + l * 16) = make_uint4(ph[0], ph[1], ph[2], ph[3]);
        *(uint4*)(As + 8192 + (w * 2 + ks) * 512 + l * 16) = make_uint4(pl[0], pl[1], pl[2], pl[3]);
    }
}

__device__ __forceinline__ void loadB_async(char* sm, int stage, int chunk, int tid) {
    const char* src = (const char*)g_zfrag + (size_t)chunk * 16384;
    char* Bs = sm + stage * STAGE_BYTES + 16384;
    #pragma unroll
    for (int q = 0; q < 4; ++q)
        cp16(Bs + (tid + q * 256) * 16, src + (size_t)(tid + q * 256) * 16);
    cp_commit();
}

__global__ __launch_bounds__(256, 1) void k_gemm_mma(const float* __restrict__ motif) {
    extern __shared__ char sm[];
    int tid = threadIdx.x;
    int w = tid >> 5, l = tid & 31;
    int wm = w & 1, wn = w >> 1;
    int g = l >> 2, cb = l & 3;
    int c0 = cb * 2;

    for (int u = blockIdx.x; u < NUNITS; u += GRID_GEMM) {
        int jt = u % NJT, ksp = u / NJT;
        int J0 = jt * 128;
        int ch0 = (ksp * NCHUNK) / KSPL;
        int ch1 = ((ksp + 1) * NCHUNK) / KSPL;
        int nch = ch1 - ch0;

        float4 acc[4][4];
        #pragma unroll
        for (int a = 0; a < 4; ++a)
            #pragma unroll
            for (int b = 0; b < 4; ++b) acc[a][b] = make_float4(0.f, 0.f, 0.f, 0.f);

        float apre[16];
        prefetchA(apre, motif, ch0, J0, w, g, c0);
        loadB_async(sm, 0, ch0, tid);                 // group B0
        if (nch > 1) loadB_async(sm, 1, ch0 + 1, tid);// group B1
        stsA(sm, apre, w, l);                         // A(0) -> stage 0
        if (nch > 1) prefetchA(apre, motif, ch0 + 1, J0, w, g, c0);

        for (int cc = 0; cc < nch; ++cc) {
            int s = cc % NSTAGE;
            char* As = sm + s * STAGE_BYTES;
            char* Bs = As + 16384;

            if (cc + 1 < nch) stsA(sm + ((cc + 1) % NSTAGE) * STAGE_BYTES, apre, w, l);
            if (cc + 2 < nch) prefetchA(apre, motif, ch0 + cc + 2, J0, w, g, c0);

            if (cc + 1 < nch) cp_wait<1>(); else cp_wait<0>();
            __syncthreads();

            if (cc + 2 < nch) loadB_async(sm, (cc + 2) % NSTAGE, ch0 + cc + 2, tid);

            // MMA: 2 k-steps x (4x4 tiles) x 3 split terms
            #pragma unroll
            for (int ks = 0; ks < 2; ++ks) {
                uint2 bh[4], bl[4];
                uint4 ah[4], al[4];
                #pragma unroll
                for (int ntl = 0; ntl < 4; ++ntl) {
                    int nto = ((wn * 4 + ntl) * 2 + ks) * 256 + l * 8;
                    bh[ntl] = *(const uint2*)(Bs + nto);
                    bl[ntl] = *(const uint2*)(Bs + 8192 + nto);
                }
                #pragma unroll
                for (int mtl = 0; mtl < 4; ++mtl) {
                    int mto = ((wm * 4 + mtl) * 2 + ks) * 512 + l * 16;
                    ah[mtl] = *(const uint4*)(As + mto);
                    al[mtl] = *(const uint4*)(As + 8192 + mto);
                }
                #pragma unroll
                for (int mtl = 0; mtl < 4; ++mtl)
                    #pragma unroll
                    for (int ntl = 0; ntl < 4; ++ntl) {
                        mma16(acc[mtl][ntl], ah[mtl], bh[ntl]);
                        mma16(acc[mtl][ntl], ah[mtl], bl[ntl]);
                        mma16(acc[mtl][ntl], al[mtl], bh[ntl]);
                    }
            }
        }

        // epilogue: write partials (rescale by 1/2048)
        float* Up = g_Upart[ksp];
        #pragma unroll
        for (int mtl = 0; mtl < 4; ++mtl) {
            int r0 = J0 + wm * 64 + mtl * 16 + g;
            #pragma unroll
            for (int ntl = 0; ntl < 4; ++ntl) {
                int d0 = wn * 32 + ntl * 8 + cb * 2;
                float4 a = acc[mtl][ntl];
                if (r0 < NN_)
                    *(float2*)&Up[(size_t)r0 * 128 + d0] =
                        make_float2(a.x * INV_ZSCALE, a.y * INV_ZSCALE);
                if (r0 + 8 < NN_)
                    *(float2*)&Up[(size_t)(r0 + 8) * 128 + d0] =
                        make_float2(a.z * INV_ZSCALE, a.w * INV_ZSCALE);
            }
        }
        __syncthreads();   // protect stage reuse by next unit
    }
}

// ---------------- K4: epilogue — h = tanh(dinv*(U+z)+b), scores ----------------
__global__ __launch_bounds__(256) void k_epi(const float* __restrict__ b_gcn,
                                             const float* __restrict__ w_score,
                                             const float* __restrict__ b_score,
                                             float* __restrict__ out_scores) {
    int warp = threadIdx.x >> 5;
    int lane = threadIdx.x & 31;
    int j = blockIdx.x * 8 + warp;
    if (j >= NN_) return;
    float dj = g_dinv[j];
    float ssum = 0.f;
    #pragma unroll
    for (int q = 0; q < 4; ++q) {
        int d = lane + 32 * q;
        size_t off = (size_t)j * DD_ + d;
        float u = 0.f;
        #pragma unroll
        for (int s = 0; s < KSPL; ++s) u += g_Upart[s][off];
        u += g_z[off];
        float hh = tanhf(dj * u + b_gcn[d]);
        g_h[off] = hh;
        ssum += hh * w_score[d];
    }
    #pragma unroll
    for (int o = 16; o; o >>= 1) ssum += __shfl_down_sync(0xffffffffu, ssum, o);
    if (lane == 0) {
        float sc = ssum + b_score[0];
        g_scores[j] = sc;
        out_scores[j] = sc;
    }
}

// ---------------- K5: exact top-k selection ----------------
__global__ __launch_bounds__(1024) void k_select(float* __restrict__ out_topidx_f) {
    __shared__ unsigned keys[NN_];
    __shared__ unsigned hist[256];
    __shared__ unsigned sc[1024];
    __shared__ unsigned sh_prefix, sh_r, sh_cg;
    int tid = threadIdx.x;

    for (int i = tid; i < NN_; i += 1024) {
        unsigned u = __float_as_uint(g_scores[i]);
        u = (u & 0x80000000u) ? ~u : (u | 0x80000000u);
        keys[i] = u;
    }
    if (tid == 0) { sh_prefix = 0u; sh_r = KSEL; sh_cg = 0u; }
    __syncthreads();

    for (int p = 3; p >= 0; --p) {
        if (tid < 256) hist[tid] = 0u;
        __syncthreads();
        unsigned msk  = (p == 3) ? 0u : (0xFFFFFFFFu << (8 * (p + 1)));
        unsigned pref = sh_prefix;
        for (int i = tid; i < NN_; i += 1024) {
            unsigned kk = keys[i];
            if ((kk & msk) == pref) atomicAdd(&hist[(kk >> (8 * p)) & 255], 1u);
        }
        __syncthreads();
        if (tid == 0) {
            unsigned r = sh_r, c = 0; int b = 0;
            for (b = 255; b >= 0; --b) {
                if (c + hist[b] >= r) break;
                c += hist[b];
            }
            sh_r = r - c;
            sh_prefix = pref | ((unsigned)b << (8 * p));
        }
        __syncthreads();
    }
    unsigned T = sh_prefix;

    {
        unsigned c = 0;
        for (int i = tid; i < NN_; i += 1024) c += (keys[i] > T);
        atomicAdd(&sh_cg, c);
    }
    __syncthreads();
    unsigned ties_needed = KSEL - sh_cg;

    int base = tid * 10;
    int end  = base + 10; if (end > NN_) end = NN_;
    if (base > NN_) base = NN_;

    unsigned tc = 0;
    for (int i = base; i < end; ++i) tc += (keys[i] == T);
    sc[tid] = tc; __syncthreads();
    for (int off = 1; off < 1024; off <<= 1) {
        unsigned v = (tid >= off) ? sc[tid - off] : 0u;
        __syncthreads(); sc[tid] += v; __syncthreads();
    }
    unsigned tie_excl = sc[tid] - tc;
    __syncthreads();

    unsigned scnt = 0;
    {
        unsigned tr = tie_excl;
        for (int i = base; i < end; ++i) {
            unsigned kk = keys[i];
            bool tie = (kk == T);
            bool sel = (kk > T) || (tie && tr < ties_needed);
            tr += tie; scnt += sel;
        }
    }
    sc[tid] = scnt; __syncthreads();
    for (int off = 1; off < 1024; off <<= 1) {
        unsigned v = (tid >= off) ? sc[tid - off] : 0u;
        __syncthreads(); sc[tid] += v; __syncthreads();
    }
    unsigned pos = sc[tid] - scnt;
    {
        unsigned tr = tie_excl;
        for (int i = base; i < end; ++i) {
            unsigned kk = keys[i];
            bool tie = (kk == T);
            bool sel = (kk > T) || (tie && tr < ties_needed);
            tr += tie;
            if (sel) {
                g_topidx[pos] = i;
                out_topidx_f[pos] = (float)i;
                ++pos;
            }
        }
    }
}

// ---------------- K6: x_pool gather (float4) ----------------
__global__ void k_xpool(float* __restrict__ out_x) {
    int t = blockIdx.x * 256 + threadIdx.x;
    if (t >= KSEL * DD_ / 4) return;
    int r  = t >> 5;
    int d4 = (t & 31) * 4;
    float4 v = *(const float4*)&g_h[(size_t)g_topidx[r] * DD_ + d4];
    *(float4*)&out_x[(size_t)r * DD_ + d4] = v;
}

// ---------------- K7: adjacency_pool & motif_pool gathers (8 c's / thread) ----------------
__global__ __launch_bounds__(256) void k_pool(const float* __restrict__ adjacency,
                                              const float* __restrict__ motif,
                                              float* __restrict__ out_adj,
                                              float* __restrict__ out_motif) {
    int r = blockIdx.y;
    int c0 = (blockIdx.x * 256 + threadIdx.x) * 8;
    if (c0 >= KSEL) return;
    int ri = g_topidx[r];
    size_t rb = (size_t)ri * NN_;
    int4 cia = *(const int4*)&g_topidx[c0];
    int4 cib = *(const int4*)&g_topidx[c0 + 4];
    float va[8], vm[8];
    va[0] = __ldg(&adjacency[rb + cia.x]);  vm[0] = __ldg(&motif[rb + cia.x]);
    va[1] = __ldg(&adjacency[rb + cia.y]);  vm[1] = __ldg(&motif[rb + cia.y]);
    va[2] = __ldg(&adjacency[rb + cia.z]);  vm[2] = __ldg(&motif[rb + cia.z]);
    va[3] = __ldg(&adjacency[rb + cia.w]);  vm[3] = __ldg(&motif[rb + cia.w]);
    va[4] = __ldg(&adjacency[rb + cib.x]);  vm[4] = __ldg(&motif[rb + cib.x]);
    va[5] = __ldg(&adjacency[rb + cib.y]);  vm[5] = __ldg(&motif[rb + cib.y]);
    va[6] = __ldg(&adjacency[rb + cib.z]);  vm[6] = __ldg(&motif[rb + cib.z]);
    va[7] = __ldg(&adjacency[rb + cib.w]);  vm[7] = __ldg(&motif[rb + cib.w]);
    size_t dst = (size_t)r * KSEL + c0;
    *(float4*)&out_adj[dst]       = make_float4(va[0], va[1], va[2], va[3]);
    *(float4*)&out_adj[dst + 4]   = make_float4(va[4], va[5], va[6], va[7]);
    *(float4*)&out_motif[dst]     = make_float4(vm[0], vm[1], vm[2], vm[3]);
    *(float4*)&out_motif[dst + 4] = make_float4(vm[4], vm[5], vm[6], vm[7]);
}

// ---------------- launch ----------------
extern "C" void kernel_launch(void* const* d_in, const int* in_sizes, int n_in,
                              void* d_out, int out_size) {
    const float* x       = (const float*)d_in[0];
    const float* adj     = (const float*)d_in[1];
    const float* motif   = (const float*)d_in[2];
    const float* W_gcn   = (const float*)d_in[3];
    const float* b_gcn   = (const float*)d_in[4];
    const float* w_score = (const float*)d_in[5];
    const float* b_score = (const float*)d_in[6];
    float* out = (float*)d_out;

    float* out_x      = out + OFF_XPOOL;
    float* out_adj    = out + OFF_ADJ;
    float* out_motif  = out + OFF_MOTIF;
    float* out_scores = out + OFF_SCORES;
    float* out_tif    = out + OFF_TOPIDX;

    cudaFuncSetAttribute(k_gemm_mma, cudaFuncAttributeMaxDynamicSharedMemorySize, GEMM_SMEM);

    k_transW<<<16, 1024>>>(W_gcn);
    k_deg_part<<<dim3(40, DEG_CHUNKS), 256>>>(motif);
    k_deg_fin<<<40, 256>>>();
    k_z<<<626, 128>>>(x);              // 626 blocks: last zeroes chunk 312 upper half
    k_gemm_mma<<<GRID_GEMM, 256, GEMM_SMEM>>>(motif);
    k_epi<<<1250, 256>>>(b_gcn, w_score, b_score, out_scores);
    k_select<<<1, 1024>>>(out_tif);
    k_xpool<<<625, 256>>>(out_x);
    k_pool<<<dim3(3, KSEL), 256>>>(adj, motif, out_adj, out_motif);
}